// round 1
// baseline (speedup 1.0000x reference)
#include <cuda_runtime.h>
#include <math.h>

// Problem constants
#define TOK   8192      // B*S tokens
#define DIM   1024      // D
#define NEXP  8         // E
#define HID   4096      // H

// ---------------- scratch (static device globals; no cudaMalloc) ------------
__device__ int   g_expert[TOK];
__device__ int   g_counts[NEXP];
__device__ int   g_offsets[NEXP];
__device__ int   g_cursor[NEXP];
__device__ int   g_tok[TOK];                       // permuted token ids, grouped by expert
__device__ float g_xg[(size_t)TOK * DIM];          // gathered x rows (32 MB)
__device__ float g_h [(size_t)TOK * HID];          // intermediate activations (128 MB)

// ---------------- init ------------------------------------------------------
__global__ void k_init() {
    int i = threadIdx.x;
    if (i < NEXP) { g_counts[i] = 0; g_cursor[i] = 0; }
}

// ---------------- router: one warp per token --------------------------------
__global__ void k_router(const float* __restrict__ x,
                         const float* __restrict__ Wr,
                         const float* __restrict__ br) {
    int warp = (blockIdx.x * blockDim.x + threadIdx.x) >> 5;
    int lane = threadIdx.x & 31;
    if (warp >= TOK) return;

    float acc[NEXP];
#pragma unroll
    for (int e = 0; e < NEXP; e++) acc[e] = 0.f;

    const float* xr = x + (size_t)warp * DIM;
    for (int d = lane; d < DIM; d += 32) {
        float xv = xr[d];
        const float4 w0 = *(const float4*)(Wr + (size_t)d * NEXP);
        const float4 w1 = *(const float4*)(Wr + (size_t)d * NEXP + 4);
        acc[0] += xv * w0.x; acc[1] += xv * w0.y; acc[2] += xv * w0.z; acc[3] += xv * w0.w;
        acc[4] += xv * w1.x; acc[5] += xv * w1.y; acc[6] += xv * w1.z; acc[7] += xv * w1.w;
    }
#pragma unroll
    for (int e = 0; e < NEXP; e++) {
#pragma unroll
        for (int off = 16; off > 0; off >>= 1)
            acc[e] += __shfl_xor_sync(0xFFFFFFFFu, acc[e], off);
    }
    if (lane == 0) {
        // softmax is monotone -> argmax of logits; strict '>' keeps first index
        float best = acc[0] + br[0]; int bi = 0;
#pragma unroll
        for (int e = 1; e < NEXP; e++) {
            float v = acc[e] + br[e];
            if (v > best) { best = v; bi = e; }
        }
        g_expert[warp] = bi;
        atomicAdd(&g_counts[bi], 1);
    }
}

// ---------------- exclusive scan over 8 counts ------------------------------
__global__ void k_scan() {
    if (threadIdx.x == 0) {
        int s = 0;
        for (int e = 0; e < NEXP; e++) { g_offsets[e] = s; s += g_counts[e]; }
    }
}

// ---------------- scatter token ids into per-expert segments ----------------
__global__ void k_scatter() {
    int t = blockIdx.x * blockDim.x + threadIdx.x;
    if (t >= TOK) return;
    int e = g_expert[t];
    int pos = g_offsets[e] + atomicAdd(&g_cursor[e], 1);
    g_tok[pos] = t;
}

// ---------------- gather x rows into permuted contiguous buffer -------------
__global__ void k_gather(const float* __restrict__ x) {
    int pos = blockIdx.x;                 // 0..TOK-1
    int t   = g_tok[pos];
    const float4* src = (const float4*)(x + (size_t)t * DIM);
    float4* dst = (float4*)(g_xg + (size_t)pos * DIM);
    dst[threadIdx.x] = src[threadIdx.x];  // 256 threads * float4 = 1024 floats
}

// ---------------- GEMM1: h = gelu(Xg @ W1[e] + b1[e]) -----------------------
// Block tile 128x128, BK=8, 256 threads, 8x8 per thread.
__global__ __launch_bounds__(256, 2)
void k_gemm1(const float* __restrict__ W1, const float* __restrict__ b1) {
    __shared__ float As[8][128];
    __shared__ float Bs[8][132];

    const int e    = blockIdx.z;
    const int cnt  = g_counts[e];
    const int row0 = blockIdx.y * 128;
    if (row0 >= cnt) return;
    const int base = g_offsets[e];
    const int col0 = blockIdx.x * 128;

    const float* A = g_xg + (size_t)base * DIM;
    const float* B = W1 + (size_t)e * DIM * HID;

    const int tid = threadIdx.x;
    const int tx = tid & 15, ty = tid >> 4;

    const int a_row = tid >> 1;
    const int a_k4  = (tid & 1) * 4;
    const int b_kk  = tid >> 5;
    const int b_c4  = (tid & 31) * 4;

    float acc[8][8];
#pragma unroll
    for (int i = 0; i < 8; i++)
#pragma unroll
        for (int j = 0; j < 8; j++) acc[i][j] = 0.f;

    for (int k0 = 0; k0 < DIM; k0 += 8) {
        float4 av = make_float4(0.f, 0.f, 0.f, 0.f);
        if (row0 + a_row < cnt)
            av = *(const float4*)(A + (size_t)(row0 + a_row) * DIM + k0 + a_k4);
        As[a_k4 + 0][a_row] = av.x;
        As[a_k4 + 1][a_row] = av.y;
        As[a_k4 + 2][a_row] = av.z;
        As[a_k4 + 3][a_row] = av.w;

        float4 bv = *(const float4*)(B + (size_t)(k0 + b_kk) * HID + col0 + b_c4);
        *(float4*)&Bs[b_kk][b_c4] = bv;
        __syncthreads();

#pragma unroll
        for (int kk = 0; kk < 8; kk++) {
            float a_frag[8], b_frag[8];
            *(float4*)&a_frag[0] = *(const float4*)&As[kk][ty * 8];
            *(float4*)&a_frag[4] = *(const float4*)&As[kk][ty * 8 + 4];
            *(float4*)&b_frag[0] = *(const float4*)&Bs[kk][tx * 8];
            *(float4*)&b_frag[4] = *(const float4*)&Bs[kk][tx * 8 + 4];
#pragma unroll
            for (int i = 0; i < 8; i++)
#pragma unroll
                for (int j = 0; j < 8; j++)
                    acc[i][j] = fmaf(a_frag[i], b_frag[j], acc[i][j]);
        }
        __syncthreads();
    }

    float bias[8];
#pragma unroll
    for (int j = 0; j < 8; j++) bias[j] = b1[(size_t)e * HID + col0 + tx * 8 + j];

#pragma unroll
    for (int i = 0; i < 8; i++) {
        int r = row0 + ty * 8 + i;
        if (r >= cnt) continue;
        float vals[8];
#pragma unroll
        for (int j = 0; j < 8; j++) {
            float v = acc[i][j] + bias[j];
            vals[j] = 0.5f * v * (1.0f + erff(v * 0.70710678118654752f));
        }
        float* dst = g_h + (size_t)(base + r) * HID + col0 + tx * 8;
        *(float4*)(dst)     = *(float4*)&vals[0];
        *(float4*)(dst + 4) = *(float4*)&vals[4];
    }
}

// ---------------- GEMM2: out[tok] = h @ W2[e] + b2[e] (scattered) -----------
__global__ __launch_bounds__(256, 2)
void k_gemm2(const float* __restrict__ W2, const float* __restrict__ b2,
             float* __restrict__ out) {
    __shared__ float As[8][128];
    __shared__ float Bs[8][132];

    const int e    = blockIdx.z;
    const int cnt  = g_counts[e];
    const int row0 = blockIdx.y * 128;
    if (row0 >= cnt) return;
    const int base = g_offsets[e];
    const int col0 = blockIdx.x * 128;

    const float* A = g_h + (size_t)base * HID;
    const float* B = W2 + (size_t)e * HID * DIM;

    const int tid = threadIdx.x;
    const int tx = tid & 15, ty = tid >> 4;

    const int a_row = tid >> 1;
    const int a_k4  = (tid & 1) * 4;
    const int b_kk  = tid >> 5;
    const int b_c4  = (tid & 31) * 4;

    float acc[8][8];
#pragma unroll
    for (int i = 0; i < 8; i++)
#pragma unroll
        for (int j = 0; j < 8; j++) acc[i][j] = 0.f;

    for (int k0 = 0; k0 < HID; k0 += 8) {
        float4 av = make_float4(0.f, 0.f, 0.f, 0.f);
        if (row0 + a_row < cnt)
            av = *(const float4*)(A + (size_t)(row0 + a_row) * HID + k0 + a_k4);
        As[a_k4 + 0][a_row] = av.x;
        As[a_k4 + 1][a_row] = av.y;
        As[a_k4 + 2][a_row] = av.z;
        As[a_k4 + 3][a_row] = av.w;

        float4 bv = *(const float4*)(B + (size_t)(k0 + b_kk) * DIM + col0 + b_c4);
        *(float4*)&Bs[b_kk][b_c4] = bv;
        __syncthreads();

#pragma unroll
        for (int kk = 0; kk < 8; kk++) {
            float a_frag[8], b_frag[8];
            *(float4*)&a_frag[0] = *(const float4*)&As[kk][ty * 8];
            *(float4*)&a_frag[4] = *(const float4*)&As[kk][ty * 8 + 4];
            *(float4*)&b_frag[0] = *(const float4*)&Bs[kk][tx * 8];
            *(float4*)&b_frag[4] = *(const float4*)&Bs[kk][tx * 8 + 4];
#pragma unroll
            for (int i = 0; i < 8; i++)
#pragma unroll
                for (int j = 0; j < 8; j++)
                    acc[i][j] = fmaf(a_frag[i], b_frag[j], acc[i][j]);
        }
        __syncthreads();
    }

    float bias[8];
#pragma unroll
    for (int j = 0; j < 8; j++) bias[j] = b2[(size_t)e * DIM + col0 + tx * 8 + j];

#pragma unroll
    for (int i = 0; i < 8; i++) {
        int r = row0 + ty * 8 + i;
        if (r >= cnt) continue;
        int t = g_tok[base + r];
        float vals[8];
#pragma unroll
        for (int j = 0; j < 8; j++) vals[j] = acc[i][j] + bias[j];
        float* dst = out + (size_t)t * DIM + col0 + tx * 8;
        *(float4*)(dst)     = *(float4*)&vals[0];
        *(float4*)(dst + 4) = *(float4*)&vals[4];
    }
}

// ---------------- launch -----------------------------------------------------
extern "C" void kernel_launch(void* const* d_in, const int* in_sizes, int n_in,
                              void* d_out, int out_size) {
    const float* x  = (const float*)d_in[0];
    const float* Wr = (const float*)d_in[1];
    const float* br = (const float*)d_in[2];
    const float* W1 = (const float*)d_in[3];
    const float* b1 = (const float*)d_in[4];
    const float* W2 = (const float*)d_in[5];
    const float* b2 = (const float*)d_in[6];
    float* out = (float*)d_out;

    k_init<<<1, 32>>>();
    k_router<<<TOK / 8, 256>>>(x, Wr, br);      // 8 warps/block, 1 warp/token
    k_scan<<<1, 32>>>();
    k_scatter<<<TOK / 256, 256>>>();
    k_gather<<<TOK, 256>>>(x);
    k_gemm1<<<dim3(HID / 128, TOK / 128, NEXP), 256>>>(W1, b1);
    k_gemm2<<<dim3(DIM / 128, TOK / 128, NEXP), 256>>>(W2, b2, out);
}

// round 3
// speedup vs baseline: 1.7585x; 1.7585x over previous
#include <cuda_runtime.h>
#include <cuda_bf16.h>
#include <math.h>
#include <stdint.h>

#define TOK   8192
#define DIM   1024
#define NEXP  8
#define HID   4096

// ------------------------- device scratch (no cudaMalloc) -------------------
__device__ int   g_expert[TOK];
__device__ int   g_counts[NEXP];
__device__ int   g_offsets[NEXP];
__device__ int   g_cursor[NEXP];
__device__ int   g_tok[TOK];
__device__ float g_h  [(size_t)TOK  * HID];          // permuted activations
__device__ float g_w1t[(size_t)NEXP * DIM * HID];    // W1^T: [e][h][d]
__device__ float g_w2t[(size_t)NEXP * DIM * HID];    // W2^T: [e][d][h]

// ------------------------- helpers ------------------------------------------
__device__ __forceinline__ uint32_t smem_u32(const void* p) {
    uint32_t a;
    asm("{ .reg .u64 t; cvta.to.shared.u64 t, %1; cvt.u32.u64 %0, t; }" : "=r"(a) : "l"(p));
    return a;
}

#define LDSM4(r, addr)                                                          \
    asm volatile("ldmatrix.sync.aligned.m8n8.x4.shared.b16 {%0,%1,%2,%3}, [%4];" \
        : "=r"((r)[0]), "=r"((r)[1]), "=r"((r)[2]), "=r"((r)[3]) : "r"(addr))

#define MMA_BF16(d, a, b)                                                       \
    asm volatile("mma.sync.aligned.m16n8k16.row.col.f32.bf16.bf16.f32 "         \
        "{%0,%1,%2,%3},{%4,%5,%6,%7},{%8,%9},{%0,%1,%2,%3};"                    \
        : "+f"((d)[0]), "+f"((d)[1]), "+f"((d)[2]), "+f"((d)[3])                 \
        : "r"((a)[0]), "r"((a)[1]), "r"((a)[2]), "r"((a)[3]),                    \
          "r"((b)[0]), "r"((b)[1]))

#define STS128U(addr, a, b, c, d)                                               \
    asm volatile("st.shared.v4.b32 [%0], {%1,%2,%3,%4};"                         \
        :: "r"(addr), "r"(a), "r"(b), "r"(c), "r"(d) : "memory")

__device__ __forceinline__ uint16_t bf16bits(float f) {
    __nv_bfloat16 h = __float2bfloat16(f);
    return *reinterpret_cast<uint16_t*>(&h);
}
// pack two floats -> bf16x2 hi word + bf16x2 lo word (element k in low half)
__device__ __forceinline__ void split2(float x, float y, uint32_t& hi, uint32_t& lo) {
    uint16_t hx = bf16bits(x), hy = bf16bits(y);
    __nv_bfloat16 bx = *reinterpret_cast<__nv_bfloat16*>(&hx);
    __nv_bfloat16 by = *reinterpret_cast<__nv_bfloat16*>(&hy);
    uint16_t lx = bf16bits(x - __bfloat162float(bx));
    uint16_t ly = bf16bits(y - __bfloat162float(by));
    hi = (uint32_t)hx | ((uint32_t)hy << 16);
    lo = (uint32_t)lx | ((uint32_t)ly << 16);
}

// swizzled byte offset of 16B chunk within a 128x32-bf16 tile (64B rows)
__device__ __forceinline__ uint32_t swz(uint32_t row, uint32_t chunk) {
    return row * 64u + (((chunk ^ (row >> 1)) & 3u) << 4);
}

// ------------------------- small kernels ------------------------------------
__global__ void k_init() {
    int i = threadIdx.x;
    if (i < NEXP) { g_counts[i] = 0; g_cursor[i] = 0; }
}

__global__ void k_router(const float* __restrict__ x,
                         const float* __restrict__ Wr,
                         const float* __restrict__ br) {
    int warp = (blockIdx.x * blockDim.x + threadIdx.x) >> 5;
    int lane = threadIdx.x & 31;
    if (warp >= TOK) return;
    float acc[NEXP];
#pragma unroll
    for (int e = 0; e < NEXP; e++) acc[e] = 0.f;
    const float* xr = x + (size_t)warp * DIM;
    for (int d = lane; d < DIM; d += 32) {
        float xv = xr[d];
        float4 w0 = *(const float4*)(Wr + (size_t)d * NEXP);
        float4 w1 = *(const float4*)(Wr + (size_t)d * NEXP + 4);
        acc[0] += xv * w0.x; acc[1] += xv * w0.y; acc[2] += xv * w0.z; acc[3] += xv * w0.w;
        acc[4] += xv * w1.x; acc[5] += xv * w1.y; acc[6] += xv * w1.z; acc[7] += xv * w1.w;
    }
#pragma unroll
    for (int e = 0; e < NEXP; e++)
#pragma unroll
        for (int off = 16; off > 0; off >>= 1)
            acc[e] += __shfl_xor_sync(0xFFFFFFFFu, acc[e], off);
    if (lane == 0) {
        float best = acc[0] + br[0]; int bi = 0;
#pragma unroll
        for (int e = 1; e < NEXP; e++) {
            float v = acc[e] + br[e];
            if (v > best) { best = v; bi = e; }
        }
        g_expert[warp] = bi;
        atomicAdd(&g_counts[bi], 1);
    }
}

__global__ void k_scan() {
    if (threadIdx.x == 0) {
        int s = 0;
        for (int e = 0; e < NEXP; e++) { g_offsets[e] = s; s += g_counts[e]; }
    }
}

__global__ void k_scatter() {
    int t = blockIdx.x * blockDim.x + threadIdx.x;
    if (t >= TOK) return;
    int e = g_expert[t];
    g_tok[g_offsets[e] + atomicAdd(&g_cursor[e], 1)] = t;
}

// transpose per expert: src [E][R][C] -> dst [E][C][R]
__global__ void k_transpose(const float* __restrict__ src, float* __restrict__ dst,
                            int R, int C) {
    __shared__ float tile[32][33];
    const float* s = src + (size_t)blockIdx.z * R * C;
    float*       d = dst + (size_t)blockIdx.z * R * C;
    int c0 = blockIdx.x * 32, r0 = blockIdx.y * 32;
#pragma unroll
    for (int i = threadIdx.y; i < 32; i += 8)
        tile[i][threadIdx.x] = s[(size_t)(r0 + i) * C + c0 + threadIdx.x];
    __syncthreads();
#pragma unroll
    for (int i = threadIdx.y; i < 32; i += 8)
        d[(size_t)(c0 + i) * R + r0 + threadIdx.x] = tile[threadIdx.x][i];
}

// ------------------------- bf16x3 HMMA grouped GEMM --------------------------
// D[m][n] = sum_k A[m][k] * B[n][k]; 128x128 CTA tile, BK=32, double-buffered.
// smem per stage: Ah(8K) Al(8K) Bh(8K) Bl(8K) = 32KB; two stages = 64KB.
template<int KTOT, int NTOT, bool GELU_ACT, bool GATHER_A, bool SCATTER_OUT>
__global__ __launch_bounds__(256)
void k_mma(const float* __restrict__ Abase, const float* __restrict__ Bt,
           const float* __restrict__ bias, float* __restrict__ Out) {
    extern __shared__ char smem[];
    const int e    = blockIdx.z;
    const int cnt  = g_counts[e];
    const int row0 = blockIdx.y * 128;
    if (row0 >= cnt) return;
    const int base = g_offsets[e];
    const int col0 = blockIdx.x * 128;

    const uint32_t sb = smem_u32(smem);
    const int tid  = threadIdx.x;
    const int lane = tid & 31, warp = tid >> 5;
    const int wm = warp & 1, wn = warp >> 1;        // 2 x 4 warp grid

    // ---- producer mapping: thread -> (row = tid/2, k-half = (tid&1)*16) ----
    const int  pr = tid >> 1;
    const int  kh = tid & 1;
    const bool arow_ok = (row0 + pr) < cnt;
    const float* Arow = Abase;
    if (arow_ok) {
        if (GATHER_A) Arow = Abase + (size_t)g_tok[base + row0 + pr] * KTOT;
        else          Arow = Abase + (size_t)(base + row0 + pr) * KTOT;
    }
    const float* Brow = Bt + ((size_t)e * NTOT + (col0 + pr)) * KTOT;

    const uint32_t stA0 = swz((uint32_t)pr, (uint32_t)(kh * 2));
    const uint32_t stA1 = swz((uint32_t)pr, (uint32_t)(kh * 2 + 1));

    // ---- consumer (ldmatrix) mapping ----
    const uint32_t g  = (uint32_t)lane >> 3;
    const uint32_t lr = (uint32_t)lane & 7;
    const uint32_t rowA = (uint32_t)(wm * 64) + (g & 1) * 8 + lr;
    const uint32_t chA  = g >> 1;
    const uint32_t rowB = (uint32_t)(wn * 32) + (g >> 1) * 8 + lr;
    const uint32_t chB  = g & 1;

    float acc[4][4][4];
#pragma unroll
    for (int i = 0; i < 4; i++)
#pragma unroll
        for (int j = 0; j < 4; j++)
#pragma unroll
            for (int q = 0; q < 4; q++) acc[i][j][q] = 0.f;

    float4 a4[4], b4[4];

    // producer: load 16 A + 16 B floats for chunk c
    auto ldg_stage = [&](int c) {
        const size_t koff = (size_t)c * 32 + kh * 16;
#pragma unroll
        for (int j = 0; j < 4; j++) {
            a4[j] = arow_ok ? *(const float4*)(Arow + koff + j * 4)
                            : make_float4(0.f, 0.f, 0.f, 0.f);
            b4[j] = *(const float4*)(Brow + koff + j * 4);
        }
    };
    // producer: split + store into stage s
    auto sts_stage = [&](int s) {
        const uint32_t st = sb + (uint32_t)s * 32768u;
        uint32_t h[8], l[8];
        split2(a4[0].x, a4[0].y, h[0], l[0]); split2(a4[0].z, a4[0].w, h[1], l[1]);
        split2(a4[1].x, a4[1].y, h[2], l[2]); split2(a4[1].z, a4[1].w, h[3], l[3]);
        split2(a4[2].x, a4[2].y, h[4], l[4]); split2(a4[2].z, a4[2].w, h[5], l[5]);
        split2(a4[3].x, a4[3].y, h[6], l[6]); split2(a4[3].z, a4[3].w, h[7], l[7]);
        STS128U(st + stA0,         h[0], h[1], h[2], h[3]);
        STS128U(st + stA1,         h[4], h[5], h[6], h[7]);
        STS128U(st + 8192 + stA0,  l[0], l[1], l[2], l[3]);
        STS128U(st + 8192 + stA1,  l[4], l[5], l[6], l[7]);
        split2(b4[0].x, b4[0].y, h[0], l[0]); split2(b4[0].z, b4[0].w, h[1], l[1]);
        split2(b4[1].x, b4[1].y, h[2], l[2]); split2(b4[1].z, b4[1].w, h[3], l[3]);
        split2(b4[2].x, b4[2].y, h[4], l[4]); split2(b4[2].z, b4[2].w, h[5], l[5]);
        split2(b4[3].x, b4[3].y, h[6], l[6]); split2(b4[3].z, b4[3].w, h[7], l[7]);
        STS128U(st + 16384 + stA0, h[0], h[1], h[2], h[3]);
        STS128U(st + 16384 + stA1, h[4], h[5], h[6], h[7]);
        STS128U(st + 24576 + stA0, l[0], l[1], l[2], l[3]);
        STS128U(st + 24576 + stA1, l[4], l[5], l[6], l[7]);
    };

    // prologue
    ldg_stage(0);
    sts_stage(0);
    __syncthreads();

    const int NC = KTOT / 32;
    for (int c = 0; c < NC; c++) {
        if (c + 1 < NC) ldg_stage(c + 1);

        const uint32_t st = sb + (uint32_t)(c & 1) * 32768u;
#pragma unroll
        for (int kk = 0; kk < 2; kk++) {
            uint32_t ah[4][4], al[4][4], bb[4][2];
            // A hi fragments
#pragma unroll
            for (int i = 0; i < 4; i++) {
                uint32_t addr = st + swz(rowA + i * 16, kk * 2 + chA);
                LDSM4(ah[i], addr);
            }
            // B hi fragments (2 x ldmatrix.x4 covers n=32)
#pragma unroll
            for (int p = 0; p < 2; p++) {
                uint32_t t4[4];
                uint32_t addr = st + 16384u + swz(rowB + p * 16, kk * 2 + chB);
                LDSM4(t4, addr);
                bb[p * 2][0] = t4[0]; bb[p * 2][1] = t4[1];
                bb[p * 2 + 1][0] = t4[2]; bb[p * 2 + 1][1] = t4[3];
            }
#pragma unroll
            for (int i = 0; i < 4; i++)
#pragma unroll
                for (int j = 0; j < 4; j++) MMA_BF16(acc[i][j], ah[i], bb[j]);
            // A lo
#pragma unroll
            for (int i = 0; i < 4; i++) {
                uint32_t addr = st + 8192u + swz(rowA + i * 16, kk * 2 + chA);
                LDSM4(al[i], addr);
            }
#pragma unroll
            for (int i = 0; i < 4; i++)
#pragma unroll
                for (int j = 0; j < 4; j++) MMA_BF16(acc[i][j], al[i], bb[j]);
            // B lo (overwrite bb)
#pragma unroll
            for (int p = 0; p < 2; p++) {
                uint32_t t4[4];
                uint32_t addr = st + 24576u + swz(rowB + p * 16, kk * 2 + chB);
                LDSM4(t4, addr);
                bb[p * 2][0] = t4[0]; bb[p * 2][1] = t4[1];
                bb[p * 2 + 1][0] = t4[2]; bb[p * 2 + 1][1] = t4[3];
            }
#pragma unroll
            for (int i = 0; i < 4; i++)
#pragma unroll
                for (int j = 0; j < 4; j++) MMA_BF16(acc[i][j], ah[i], bb[j]);
        }

        if (c + 1 < NC) sts_stage((c + 1) & 1);
        __syncthreads();
    }

    // ---- epilogue ----
    const int qr = lane >> 2;            // 0..7
    const int qc = (lane & 3) * 2;       // 0,2,4,6
#pragma unroll
    for (int i = 0; i < 4; i++) {
#pragma unroll
        for (int h = 0; h < 2; h++) {
            const int grow = row0 + wm * 64 + i * 16 + qr + h * 8;
            if (grow >= cnt) continue;
            size_t orow = SCATTER_OUT ? (size_t)g_tok[base + grow]
                                      : (size_t)(base + grow);
            float* drow = Out + orow * NTOT;
#pragma unroll
            for (int j = 0; j < 4; j++) {
                const int col = col0 + wn * 32 + j * 8 + qc;
                float v0 = acc[i][j][h * 2 + 0] + bias[(size_t)e * NTOT + col];
                float v1 = acc[i][j][h * 2 + 1] + bias[(size_t)e * NTOT + col + 1];
                if (GELU_ACT) {
                    v0 = 0.5f * v0 * (1.0f + erff(v0 * 0.70710678118654752f));
                    v1 = 0.5f * v1 * (1.0f + erff(v1 * 0.70710678118654752f));
                }
                *(float2*)(drow + col) = make_float2(v0, v1);
            }
        }
    }
}

// ------------------------- launch --------------------------------------------
extern "C" void kernel_launch(void* const* d_in, const int* in_sizes, int n_in,
                              void* d_out, int out_size) {
    const float* x  = (const float*)d_in[0];
    const float* Wr = (const float*)d_in[1];
    const float* br = (const float*)d_in[2];
    const float* W1 = (const float*)d_in[3];
    const float* b1 = (const float*)d_in[4];
    const float* W2 = (const float*)d_in[5];
    const float* b2 = (const float*)d_in[6];
    float* out = (float*)d_out;

    float *w1t, *w2t, *hbuf;
    cudaGetSymbolAddress((void**)&w1t, g_w1t);
    cudaGetSymbolAddress((void**)&w2t, g_w2t);
    cudaGetSymbolAddress((void**)&hbuf, g_h);

    const int SMEM_DYN = 65536;
    cudaFuncSetAttribute((const void*)k_mma<DIM, HID, true,  true,  false>,
                         cudaFuncAttributeMaxDynamicSharedMemorySize, SMEM_DYN);
    cudaFuncSetAttribute((const void*)k_mma<HID, DIM, false, false, true>,
                         cudaFuncAttributeMaxDynamicSharedMemorySize, SMEM_DYN);

    k_init<<<1, 32>>>();
    k_router<<<TOK / 8, 256>>>(x, Wr, br);
    k_scan<<<1, 32>>>();
    k_scatter<<<TOK / 256, 256>>>();
    k_transpose<<<dim3(HID / 32, DIM / 32, NEXP), dim3(32, 8)>>>(W1, w1t, DIM, HID);
    k_transpose<<<dim3(DIM / 32, HID / 32, NEXP), dim3(32, 8)>>>(W2, w2t, HID, DIM);

    k_mma<DIM, HID, true,  true,  false>
        <<<dim3(HID / 128, TOK / 128, NEXP), 256, SMEM_DYN>>>(x, w1t, b1, hbuf);
    k_mma<HID, DIM, false, false, true>
        <<<dim3(DIM / 128, TOK / 128, NEXP), 256, SMEM_DYN>>>(hbuf, w2t, b2, out);
}

// round 5
// speedup vs baseline: 2.3174x; 1.3178x over previous
#include <cuda_runtime.h>
#include <cuda_bf16.h>
#include <math.h>
#include <stdint.h>

#define TOK   8192
#define DIM   1024
#define NEXP  8
#define HID   4096
#define PAD   128

// ------------------------- device scratch (no cudaMalloc) -------------------
__device__ int g_expert[TOK];
__device__ int g_counts[NEXP];
__device__ int g_offsets[NEXP];
__device__ int g_cursor[NEXP];
__device__ int g_tok[TOK];
// pre-split bf16 hi/lo buffers (zero-initialized at module load; pad rows stay 0)
__device__ __nv_bfloat16 g_xh [(size_t)(TOK + PAD) * DIM];
__device__ __nv_bfloat16 g_xl [(size_t)(TOK + PAD) * DIM];
__device__ __nv_bfloat16 g_hh [(size_t)(TOK + PAD) * HID];
__device__ __nv_bfloat16 g_hl [(size_t)(TOK + PAD) * HID];
__device__ __nv_bfloat16 g_w1h[(size_t)NEXP * DIM * HID];   // [e][h][d]
__device__ __nv_bfloat16 g_w1l[(size_t)NEXP * DIM * HID];
__device__ __nv_bfloat16 g_w2h[(size_t)NEXP * DIM * HID];   // [e][d][h]
__device__ __nv_bfloat16 g_w2l[(size_t)NEXP * DIM * HID];

// ------------------------- helpers ------------------------------------------
__device__ __forceinline__ uint32_t smem_u32(const void* p) {
    uint32_t a;
    asm("{ .reg .u64 t; cvta.to.shared.u64 t, %1; cvt.u32.u64 %0, t; }" : "=r"(a) : "l"(p));
    return a;
}
#define LDSM4(r, addr)                                                          \
    asm volatile("ldmatrix.sync.aligned.m8n8.x4.shared.b16 {%0,%1,%2,%3}, [%4];" \
        : "=r"((r)[0]), "=r"((r)[1]), "=r"((r)[2]), "=r"((r)[3]) : "r"(addr))
#define MMA_BF16(d, a, b)                                                       \
    asm volatile("mma.sync.aligned.m16n8k16.row.col.f32.bf16.bf16.f32 "         \
        "{%0,%1,%2,%3},{%4,%5,%6,%7},{%8,%9},{%0,%1,%2,%3};"                    \
        : "+f"((d)[0]), "+f"((d)[1]), "+f"((d)[2]), "+f"((d)[3])                 \
        : "r"((a)[0]), "r"((a)[1]), "r"((a)[2]), "r"((a)[3]),                    \
          "r"((b)[0]), "r"((b)[1]))
#define CP16(dst, src)                                                          \
    asm volatile("cp.async.cg.shared.global [%0], [%1], 16;" :: "r"(dst), "l"(src) : "memory")
#define CP_COMMIT() asm volatile("cp.async.commit_group;" ::: "memory")
#define CP_WAIT1()  asm volatile("cp.async.wait_group 1;"  ::: "memory")

__device__ __forceinline__ void split2(float x, float y, uint32_t& hi, uint32_t& lo) {
    __nv_bfloat16 bx = __float2bfloat16(x);
    __nv_bfloat16 by = __float2bfloat16(y);
    __nv_bfloat16 lx = __float2bfloat16(x - __bfloat162float(bx));
    __nv_bfloat16 ly = __float2bfloat16(y - __bfloat162float(by));
    hi = (uint32_t)*(uint16_t*)&bx | ((uint32_t)*(uint16_t*)&by << 16);
    lo = (uint32_t)*(uint16_t*)&lx | ((uint32_t)*(uint16_t*)&ly << 16);
}
// swizzled byte offset of 16B chunk within a 128x32-bf16 tile (64B rows)
__device__ __forceinline__ uint32_t swz(uint32_t row, uint32_t chunk) {
    return row * 64u + (((chunk ^ (row >> 1)) & 3u) << 4);
}

// ------------------------- small kernels ------------------------------------
__global__ void k_init() {
    int i = threadIdx.x;
    if (i < NEXP) { g_counts[i] = 0; g_cursor[i] = 0; }
}

__global__ void k_router(const float* __restrict__ x,
                         const float* __restrict__ Wr,
                         const float* __restrict__ br) {
    int warp = (blockIdx.x * blockDim.x + threadIdx.x) >> 5;
    int lane = threadIdx.x & 31;
    if (warp >= TOK) return;
    float acc[NEXP];
#pragma unroll
    for (int e = 0; e < NEXP; e++) acc[e] = 0.f;
    const float* xr = x + (size_t)warp * DIM;
    for (int d = lane; d < DIM; d += 32) {
        float xv = xr[d];
        float4 w0 = *(const float4*)(Wr + (size_t)d * NEXP);
        float4 w1 = *(const float4*)(Wr + (size_t)d * NEXP + 4);
        acc[0] += xv * w0.x; acc[1] += xv * w0.y; acc[2] += xv * w0.z; acc[3] += xv * w0.w;
        acc[4] += xv * w1.x; acc[5] += xv * w1.y; acc[6] += xv * w1.z; acc[7] += xv * w1.w;
    }
#pragma unroll
    for (int e = 0; e < NEXP; e++)
#pragma unroll
        for (int off = 16; off > 0; off >>= 1)
            acc[e] += __shfl_xor_sync(0xFFFFFFFFu, acc[e], off);
    if (lane == 0) {
        float best = acc[0] + br[0]; int bi = 0;
#pragma unroll
        for (int e = 1; e < NEXP; e++) {
            float v = acc[e] + br[e];
            if (v > best) { best = v; bi = e; }
        }
        g_expert[warp] = bi;
        atomicAdd(&g_counts[bi], 1);
    }
}

__global__ void k_scan() {
    if (threadIdx.x == 0) {
        int s = 0;
        for (int e = 0; e < NEXP; e++) { g_offsets[e] = s; s += g_counts[e]; }
    }
}

__global__ void k_scatter() {
    int t = blockIdx.x * blockDim.x + threadIdx.x;
    if (t >= TOK) return;
    int e = g_expert[t];
    g_tok[g_offsets[e] + atomicAdd(&g_cursor[e], 1)] = t;
}

// gather + split x rows into permuted bf16 hi/lo
__global__ void k_gsplit(const float* __restrict__ x) {
    int pos = blockIdx.x;
    int t = g_tok[pos];
    float4 v = ((const float4*)(x + (size_t)t * DIM))[threadIdx.x];
    uint32_t h0, l0, h1, l1;
    split2(v.x, v.y, h0, l0);
    split2(v.z, v.w, h1, l1);
    size_t o = (size_t)pos * DIM + threadIdx.x * 4;
    *(uint2*)(g_xh + o) = make_uint2(h0, h1);
    *(uint2*)(g_xl + o) = make_uint2(l0, l1);
}

// transpose + split per expert: src [E][R][C] fp32 -> dst [E][C][R] bf16 hi/lo
__global__ void k_tsplit(const float* __restrict__ src,
                         __nv_bfloat16* __restrict__ dhi,
                         __nv_bfloat16* __restrict__ dlo, int R, int C) {
    __shared__ float tile[32][33];
    const float* s = src + (size_t)blockIdx.z * R * C;
    size_t dbase = (size_t)blockIdx.z * R * C;
    int c0 = blockIdx.x * 32, r0 = blockIdx.y * 32;
#pragma unroll
    for (int i = threadIdx.y; i < 32; i += 8)
        tile[i][threadIdx.x] = s[(size_t)(r0 + i) * C + c0 + threadIdx.x];
    __syncthreads();
#pragma unroll
    for (int i = threadIdx.y; i < 32; i += 8) {
        float v = tile[threadIdx.x][i];
        __nv_bfloat16 h = __float2bfloat16(v);
        __nv_bfloat16 l = __float2bfloat16(v - __bfloat162float(h));
        size_t o = dbase + (size_t)(c0 + i) * R + r0 + threadIdx.x;
        dhi[o] = h;
        dlo[o] = l;
    }
}

// ------------------------- bf16x3 HMMA grouped GEMM --------------------------
// 128x128 CTA tile, BK=32, 3-stage cp.async pipeline (32KB/stage).
// Stage math: iter c computes stage c%3 and refills stage (c+2)%3 (which was
// consumed at iter c-1 and is barrier-protected by this iter's __syncthreads).
template<int KTOT, int NTOT, bool WRITE_H, bool SCATTER_OUT>
__global__ __launch_bounds__(256)
void k_mma(const __nv_bfloat16* __restrict__ Ahi, const __nv_bfloat16* __restrict__ Alo,
           const __nv_bfloat16* __restrict__ Bhi, const __nv_bfloat16* __restrict__ Blo,
           const float* __restrict__ bias, float* __restrict__ OutF,
           __nv_bfloat16* __restrict__ Hhi, __nv_bfloat16* __restrict__ Hlo) {
    extern __shared__ char smem[];
    const int e    = blockIdx.z;
    const int cnt  = g_counts[e];
    const int row0 = blockIdx.y * 128;
    if (row0 >= cnt) return;
    const int base = g_offsets[e];
    const int col0 = blockIdx.x * 128;

    const uint32_t sb = smem_u32(smem);
    const int tid  = threadIdx.x;
    const int lane = tid & 31, warp = tid >> 5;
    const int wm = warp & 1, wn = warp >> 1;        // 2 x 4 warp grid

    // ---- producer: thread -> (row = tid/2, 32B half = tid&1); predicate-free
    const int pr = tid >> 1;
    const int hf = tid & 1;
    const size_t arow = (size_t)(base + row0 + pr);          // < TOK+PAD
    const size_t brow = (size_t)e * NTOT + col0 + pr;
    const __nv_bfloat16* pA_h = Ahi + arow * KTOT + hf * 16;
    const __nv_bfloat16* pA_l = Alo + arow * KTOT + hf * 16;
    const __nv_bfloat16* pB_h = Bhi + brow * KTOT + hf * 16;
    const __nv_bfloat16* pB_l = Blo + brow * KTOT + hf * 16;
    const uint32_t d0 = swz((uint32_t)pr, (uint32_t)(hf * 2));
    const uint32_t d1 = swz((uint32_t)pr, (uint32_t)(hf * 2 + 1));

    auto issue = [&](int c, uint32_t stoff) {
        const size_t ko = (size_t)c * 32;
        const uint32_t s0 = sb + stoff;
        CP16(s0 + d0,          pA_h + ko); CP16(s0 + d1,          pA_h + ko + 8);
        CP16(s0 + 8192  + d0,  pA_l + ko); CP16(s0 + 8192  + d1,  pA_l + ko + 8);
        CP16(s0 + 16384 + d0,  pB_h + ko); CP16(s0 + 16384 + d1,  pB_h + ko + 8);
        CP16(s0 + 24576 + d0,  pB_l + ko); CP16(s0 + 24576 + d1,  pB_l + ko + 8);
    };

    // ---- consumer (ldmatrix) mapping ----
    const uint32_t g  = (uint32_t)lane >> 3;
    const uint32_t lr = (uint32_t)lane & 7;
    const uint32_t rowA = (uint32_t)(wm * 64) + (g & 1) * 8 + lr;
    const uint32_t chA  = g >> 1;
    const uint32_t rowB = (uint32_t)(wn * 32) + (g >> 1) * 8 + lr;
    const uint32_t chB  = g & 1;

    float acc[4][4][4];
#pragma unroll
    for (int i = 0; i < 4; i++)
#pragma unroll
        for (int j = 0; j < 4; j++)
#pragma unroll
            for (int q = 0; q < 4; q++) acc[i][j][q] = 0.f;

    const int NC = KTOT / 32;
    // prologue: stages 0 and 1
    issue(0, 0);          CP_COMMIT();
    issue(1, 32768u);     CP_COMMIT();

    uint32_t st_cur = 0;          // stage offset being computed  (c % 3)
    uint32_t st_fill = 65536u;    // stage offset being refilled  ((c+2) % 3)
    for (int c = 0; c < NC; c++) {
        CP_WAIT1();
        __syncthreads();

        const uint32_t stc = sb + st_cur;
#pragma unroll
        for (int kk = 0; kk < 2; kk++) {
            uint32_t ah[4][4], al[4][4], bb[4][2];
#pragma unroll
            for (int i = 0; i < 4; i++)
                LDSM4(ah[i], stc + swz(rowA + i * 16, kk * 2 + chA));
#pragma unroll
            for (int p = 0; p < 2; p++) {
                uint32_t t4[4];
                LDSM4(t4, stc + 16384u + swz(rowB + p * 16, kk * 2 + chB));
                bb[p * 2][0] = t4[0]; bb[p * 2][1] = t4[1];
                bb[p * 2 + 1][0] = t4[2]; bb[p * 2 + 1][1] = t4[3];
            }
#pragma unroll
            for (int i = 0; i < 4; i++)
#pragma unroll
                for (int j = 0; j < 4; j++) MMA_BF16(acc[i][j], ah[i], bb[j]);
#pragma unroll
            for (int i = 0; i < 4; i++)
                LDSM4(al[i], stc + 8192u + swz(rowA + i * 16, kk * 2 + chA));
#pragma unroll
            for (int i = 0; i < 4; i++)
#pragma unroll
                for (int j = 0; j < 4; j++) MMA_BF16(acc[i][j], al[i], bb[j]);
#pragma unroll
            for (int p = 0; p < 2; p++) {
                uint32_t t4[4];
                LDSM4(t4, stc + 24576u + swz(rowB + p * 16, kk * 2 + chB));
                bb[p * 2][0] = t4[0]; bb[p * 2][1] = t4[1];
                bb[p * 2 + 1][0] = t4[2]; bb[p * 2 + 1][1] = t4[3];
            }
#pragma unroll
            for (int i = 0; i < 4; i++)
#pragma unroll
                for (int j = 0; j < 4; j++) MMA_BF16(acc[i][j], ah[i], bb[j]);
        }

        if (c + 2 < NC) issue(c + 2, st_fill);
        CP_COMMIT();                                  // commit (possibly empty)
        st_cur  = (st_cur  == 65536u) ? 0u : st_cur  + 32768u;
        st_fill = (st_fill == 65536u) ? 0u : st_fill + 32768u;
    }

    // ---- epilogue ----
    const int qr = lane >> 2;
    const int qc = (lane & 3) * 2;
#pragma unroll
    for (int i = 0; i < 4; i++) {
#pragma unroll
        for (int h = 0; h < 2; h++) {
            const int grow = row0 + wm * 64 + i * 16 + qr + h * 8;
            if (grow >= cnt) continue;
#pragma unroll
            for (int j = 0; j < 4; j++) {
                const int col = col0 + wn * 32 + j * 8 + qc;
                float v0 = acc[i][j][h * 2 + 0] + bias[(size_t)e * NTOT + col];
                float v1 = acc[i][j][h * 2 + 1] + bias[(size_t)e * NTOT + col + 1];
                if (WRITE_H) {
                    v0 = 0.5f * v0 * (1.0f + erff(v0 * 0.70710678118654752f));
                    v1 = 0.5f * v1 * (1.0f + erff(v1 * 0.70710678118654752f));
                    uint32_t hi, lo;
                    split2(v0, v1, hi, lo);
                    size_t o = (size_t)(base + grow) * NTOT + col;
                    *(uint32_t*)(Hhi + o) = hi;
                    *(uint32_t*)(Hlo + o) = lo;
                } else {
                    size_t orow = SCATTER_OUT ? (size_t)g_tok[base + grow]
                                              : (size_t)(base + grow);
                    *(float2*)(OutF + orow * NTOT + col) = make_float2(v0, v1);
                }
            }
        }
    }
}

// ------------------------- launch --------------------------------------------
extern "C" void kernel_launch(void* const* d_in, const int* in_sizes, int n_in,
                              void* d_out, int out_size) {
    const float* x  = (const float*)d_in[0];
    const float* Wr = (const float*)d_in[1];
    const float* br = (const float*)d_in[2];
    const float* W1 = (const float*)d_in[3];
    const float* b1 = (const float*)d_in[4];
    const float* W2 = (const float*)d_in[5];
    const float* b2 = (const float*)d_in[6];
    float* out = (float*)d_out;

    __nv_bfloat16 *xh, *xl, *hh, *hl, *w1h, *w1l, *w2h, *w2l;
    cudaGetSymbolAddress((void**)&xh,  g_xh);
    cudaGetSymbolAddress((void**)&xl,  g_xl);
    cudaGetSymbolAddress((void**)&hh,  g_hh);
    cudaGetSymbolAddress((void**)&hl,  g_hl);
    cudaGetSymbolAddress((void**)&w1h, g_w1h);
    cudaGetSymbolAddress((void**)&w1l, g_w1l);
    cudaGetSymbolAddress((void**)&w2h, g_w2h);
    cudaGetSymbolAddress((void**)&w2l, g_w2l);

    const int SMEM_DYN = 3 * 32768;
    cudaFuncSetAttribute((const void*)k_mma<DIM, HID, true,  false>,
                         cudaFuncAttributeMaxDynamicSharedMemorySize, SMEM_DYN);
    cudaFuncSetAttribute((const void*)k_mma<HID, DIM, false, true>,
                         cudaFuncAttributeMaxDynamicSharedMemorySize, SMEM_DYN);

    k_init<<<1, 32>>>();
    k_router<<<TOK / 8, 256>>>(x, Wr, br);
    k_scan<<<1, 32>>>();
    k_scatter<<<TOK / 256, 256>>>();
    k_gsplit<<<TOK, 256>>>(x);
    k_tsplit<<<dim3(HID / 32, DIM / 32, NEXP), dim3(32, 8)>>>(W1, w1h, w1l, DIM, HID);
    k_tsplit<<<dim3(DIM / 32, HID / 32, NEXP), dim3(32, 8)>>>(W2, w2h, w2l, HID, DIM);

    k_mma<DIM, HID, true,  false>
        <<<dim3(HID / 128, TOK / 128, NEXP), 256, SMEM_DYN>>>(
            xh, xl, w1h, w1l, b1, nullptr, hh, hl);
    k_mma<HID, DIM, false, true>
        <<<dim3(DIM / 128, TOK / 128, NEXP), 256, SMEM_DYN>>>(
            hh, hl, w2h, w2l, b2, out, nullptr, nullptr);
}

// round 6
// speedup vs baseline: 2.5350x; 1.0939x over previous
#include <cuda_runtime.h>
#include <cuda_bf16.h>
#include <math.h>
#include <stdint.h>

#define TOK   8192
#define DIM   1024
#define NEXP  8
#define HID   4096
#define PAD   128

// ------------------------- device scratch (no cudaMalloc) -------------------
__device__ int g_expert[TOK];
__device__ int g_counts[NEXP];
__device__ int g_offsets[NEXP];
__device__ int g_cursor[NEXP];
__device__ int g_tok[TOK];
// pre-split bf16 hi/lo buffers (zero-initialized at module load; pad rows stay 0)
__device__ __nv_bfloat16 g_xh [(size_t)(TOK + PAD) * DIM];
__device__ __nv_bfloat16 g_xl [(size_t)(TOK + PAD) * DIM];
__device__ __nv_bfloat16 g_hh [(size_t)(TOK + PAD) * HID];
__device__ __nv_bfloat16 g_hl [(size_t)(TOK + PAD) * HID];
__device__ __nv_bfloat16 g_w1h[(size_t)NEXP * DIM * HID];   // [e][h][d]
__device__ __nv_bfloat16 g_w1l[(size_t)NEXP * DIM * HID];
__device__ __nv_bfloat16 g_w2h[(size_t)NEXP * DIM * HID];   // [e][d][h]
__device__ __nv_bfloat16 g_w2l[(size_t)NEXP * DIM * HID];

// ------------------------- helpers ------------------------------------------
__device__ __forceinline__ uint32_t smem_u32(const void* p) {
    uint32_t a;
    asm("{ .reg .u64 t; cvta.to.shared.u64 t, %1; cvt.u32.u64 %0, t; }" : "=r"(a) : "l"(p));
    return a;
}
#define LDSM4(r, addr)                                                          \
    asm volatile("ldmatrix.sync.aligned.m8n8.x4.shared.b16 {%0,%1,%2,%3}, [%4];" \
        : "=r"((r)[0]), "=r"((r)[1]), "=r"((r)[2]), "=r"((r)[3]) : "r"(addr))
#define MMA_BF16(d, a, b)                                                       \
    asm volatile("mma.sync.aligned.m16n8k16.row.col.f32.bf16.bf16.f32 "         \
        "{%0,%1,%2,%3},{%4,%5,%6,%7},{%8,%9},{%0,%1,%2,%3};"                    \
        : "+f"((d)[0]), "+f"((d)[1]), "+f"((d)[2]), "+f"((d)[3])                 \
        : "r"((a)[0]), "r"((a)[1]), "r"((a)[2]), "r"((a)[3]),                    \
          "r"((b)[0]), "r"((b)[1]))
#define CP16(dst, src)                                                          \
    asm volatile("cp.async.cg.shared.global [%0], [%1], 16;" :: "r"(dst), "l"(src) : "memory")
#define CP_COMMIT() asm volatile("cp.async.commit_group;" ::: "memory")
#define CP_WAIT1()  asm volatile("cp.async.wait_group 1;"  ::: "memory")

__device__ __forceinline__ void split2(float x, float y, uint32_t& hi, uint32_t& lo) {
    __nv_bfloat16 bx = __float2bfloat16(x);
    __nv_bfloat16 by = __float2bfloat16(y);
    __nv_bfloat16 lx = __float2bfloat16(x - __bfloat162float(bx));
    __nv_bfloat16 ly = __float2bfloat16(y - __bfloat162float(by));
    hi = (uint32_t)*(uint16_t*)&bx | ((uint32_t)*(uint16_t*)&by << 16);
    lo = (uint32_t)*(uint16_t*)&lx | ((uint32_t)*(uint16_t*)&ly << 16);
}
// swizzled byte offset of 16B chunk within a 128x32-bf16 tile (64B rows)
__device__ __forceinline__ uint32_t swz(uint32_t row, uint32_t chunk) {
    return row * 64u + (((chunk ^ (row >> 1)) & 3u) << 4);
}

// ------------------------- small kernels ------------------------------------
__global__ void k_init() {
    int i = threadIdx.x;
    if (i < NEXP) { g_counts[i] = 0; g_cursor[i] = 0; }
}

__global__ void k_router(const float* __restrict__ x,
                         const float* __restrict__ Wr,
                         const float* __restrict__ br) {
    int warp = (blockIdx.x * blockDim.x + threadIdx.x) >> 5;
    int lane = threadIdx.x & 31;
    if (warp >= TOK) return;
    float acc[NEXP];
#pragma unroll
    for (int e = 0; e < NEXP; e++) acc[e] = 0.f;
    const float* xr = x + (size_t)warp * DIM;
    for (int d = lane; d < DIM; d += 32) {
        float xv = xr[d];
        float4 w0 = *(const float4*)(Wr + (size_t)d * NEXP);
        float4 w1 = *(const float4*)(Wr + (size_t)d * NEXP + 4);
        acc[0] += xv * w0.x; acc[1] += xv * w0.y; acc[2] += xv * w0.z; acc[3] += xv * w0.w;
        acc[4] += xv * w1.x; acc[5] += xv * w1.y; acc[6] += xv * w1.z; acc[7] += xv * w1.w;
    }
#pragma unroll
    for (int e = 0; e < NEXP; e++)
#pragma unroll
        for (int off = 16; off > 0; off >>= 1)
            acc[e] += __shfl_xor_sync(0xFFFFFFFFu, acc[e], off);
    if (lane == 0) {
        float best = acc[0] + br[0]; int bi = 0;
#pragma unroll
        for (int e = 1; e < NEXP; e++) {
            float v = acc[e] + br[e];
            if (v > best) { best = v; bi = e; }
        }
        g_expert[warp] = bi;
        atomicAdd(&g_counts[bi], 1);
    }
}

__global__ void k_scan() {
    if (threadIdx.x == 0) {
        int s = 0;
        for (int e = 0; e < NEXP; e++) { g_offsets[e] = s; s += g_counts[e]; }
    }
}

__global__ void k_scatter() {
    int t = blockIdx.x * blockDim.x + threadIdx.x;
    if (t >= TOK) return;
    int e = g_expert[t];
    g_tok[g_offsets[e] + atomicAdd(&g_cursor[e], 1)] = t;
}

// gather + split x rows into permuted bf16 hi/lo
__global__ void k_gsplit(const float* __restrict__ x) {
    int pos = blockIdx.x;
    int t = g_tok[pos];
    float4 v = ((const float4*)(x + (size_t)t * DIM))[threadIdx.x];
    uint32_t h0, l0, h1, l1;
    split2(v.x, v.y, h0, l0);
    split2(v.z, v.w, h1, l1);
    size_t o = (size_t)pos * DIM + threadIdx.x * 4;
    *(uint2*)(g_xh + o) = make_uint2(h0, h1);
    *(uint2*)(g_xl + o) = make_uint2(l0, l1);
}

// transpose + split per expert: src [E][R][C] fp32 -> dst [E][C][R] bf16 hi/lo
__global__ void k_tsplit(const float* __restrict__ src,
                         __nv_bfloat16* __restrict__ dhi,
                         __nv_bfloat16* __restrict__ dlo, int R, int C) {
    __shared__ float tile[32][33];
    const float* s = src + (size_t)blockIdx.z * R * C;
    size_t dbase = (size_t)blockIdx.z * R * C;
    int c0 = blockIdx.x * 32, r0 = blockIdx.y * 32;
#pragma unroll
    for (int i = threadIdx.y; i < 32; i += 8)
        tile[i][threadIdx.x] = s[(size_t)(r0 + i) * C + c0 + threadIdx.x];
    __syncthreads();
#pragma unroll
    for (int i = threadIdx.y; i < 32; i += 8) {
        float v = tile[threadIdx.x][i];
        __nv_bfloat16 h = __float2bfloat16(v);
        __nv_bfloat16 l = __float2bfloat16(v - __bfloat162float(h));
        size_t o = dbase + (size_t)(c0 + i) * R + r0 + threadIdx.x;
        dhi[o] = h;
        dlo[o] = l;
    }
}

// ------------------------- bf16x3 HMMA grouped GEMM --------------------------
// 128x128 CTA tile, BK=32, 3-stage cp.async pipeline (32KB/stage).
// __launch_bounds__(256, 2): 2 CTAs/SM (192KB smem, <=128 regs/thread).
// Stage math: iter c computes stage c%3 and refills stage (c+2)%3 (which was
// consumed at iter c-1 and is barrier-protected by this iter's __syncthreads).
template<int KTOT, int NTOT, bool WRITE_H, bool SCATTER_OUT>
__global__ __launch_bounds__(256, 2)
void k_mma(const __nv_bfloat16* __restrict__ Ahi, const __nv_bfloat16* __restrict__ Alo,
           const __nv_bfloat16* __restrict__ Bhi, const __nv_bfloat16* __restrict__ Blo,
           const float* __restrict__ bias, float* __restrict__ OutF,
           __nv_bfloat16* __restrict__ Hhi, __nv_bfloat16* __restrict__ Hlo) {
    extern __shared__ char smem[];
    const int e    = blockIdx.z;
    const int cnt  = g_counts[e];
    const int row0 = blockIdx.y * 128;
    if (row0 >= cnt) return;
    const int base = g_offsets[e];
    const int col0 = blockIdx.x * 128;

    const uint32_t sb = smem_u32(smem);
    const int tid  = threadIdx.x;
    const int lane = tid & 31, warp = tid >> 5;
    const int wm = warp & 1, wn = warp >> 1;        // 2 x 4 warp grid

    // ---- producer: thread -> (row = tid/2, 32B half = tid&1); predicate-free
    const int pr = tid >> 1;
    const int hf = tid & 1;
    const size_t arow = (size_t)(base + row0 + pr);          // < TOK+PAD
    const size_t brow = (size_t)e * NTOT + col0 + pr;
    const __nv_bfloat16* pA_h = Ahi + arow * KTOT + hf * 16;
    const __nv_bfloat16* pA_l = Alo + arow * KTOT + hf * 16;
    const __nv_bfloat16* pB_h = Bhi + brow * KTOT + hf * 16;
    const __nv_bfloat16* pB_l = Blo + brow * KTOT + hf * 16;
    const uint32_t d0 = swz((uint32_t)pr, (uint32_t)(hf * 2));
    const uint32_t d1 = swz((uint32_t)pr, (uint32_t)(hf * 2 + 1));

    auto issue = [&](int c, uint32_t stoff) {
        const size_t ko = (size_t)c * 32;
        const uint32_t s0 = sb + stoff;
        CP16(s0 + d0,          pA_h + ko); CP16(s0 + d1,          pA_h + ko + 8);
        CP16(s0 + 8192  + d0,  pA_l + ko); CP16(s0 + 8192  + d1,  pA_l + ko + 8);
        CP16(s0 + 16384 + d0,  pB_h + ko); CP16(s0 + 16384 + d1,  pB_h + ko + 8);
        CP16(s0 + 24576 + d0,  pB_l + ko); CP16(s0 + 24576 + d1,  pB_l + ko + 8);
    };

    // ---- consumer (ldmatrix) mapping ----
    const uint32_t g  = (uint32_t)lane >> 3;
    const uint32_t lr = (uint32_t)lane & 7;
    const uint32_t rowA = (uint32_t)(wm * 64) + (g & 1) * 8 + lr;
    const uint32_t chA  = g >> 1;
    const uint32_t rowB = (uint32_t)(wn * 32) + (g >> 1) * 8 + lr;
    const uint32_t chB  = g & 1;

    float acc[4][4][4];
#pragma unroll
    for (int i = 0; i < 4; i++)
#pragma unroll
        for (int j = 0; j < 4; j++)
#pragma unroll
            for (int q = 0; q < 4; q++) acc[i][j][q] = 0.f;

    const int NC = KTOT / 32;
    // prologue: stages 0 and 1
    issue(0, 0);          CP_COMMIT();
    issue(1, 32768u);     CP_COMMIT();

    uint32_t st_cur = 0;          // stage offset being computed  (c % 3)
    uint32_t st_fill = 65536u;    // stage offset being refilled  ((c+2) % 3)
    for (int c = 0; c < NC; c++) {
        CP_WAIT1();
        __syncthreads();

        const uint32_t stc = sb + st_cur;
#pragma unroll
        for (int kk = 0; kk < 2; kk++) {
            uint32_t ah[4][4], bb[4][2];
            // A hi fragments (kept live through the whole kk step)
#pragma unroll
            for (int i = 0; i < 4; i++)
                LDSM4(ah[i], stc + swz(rowA + i * 16, kk * 2 + chA));
            // B hi fragments
#pragma unroll
            for (int p = 0; p < 2; p++) {
                uint32_t t4[4];
                LDSM4(t4, stc + 16384u + swz(rowB + p * 16, kk * 2 + chB));
                bb[p * 2][0] = t4[0]; bb[p * 2][1] = t4[1];
                bb[p * 2 + 1][0] = t4[2]; bb[p * 2 + 1][1] = t4[3];
            }
#pragma unroll
            for (int i = 0; i < 4; i++)
#pragma unroll
                for (int j = 0; j < 4; j++) MMA_BF16(acc[i][j], ah[i], bb[j]);
            // A lo: one row at a time (register diet for 2 CTAs/SM)
#pragma unroll
            for (int i = 0; i < 4; i++) {
                uint32_t al4[4];
                LDSM4(al4, stc + 8192u + swz(rowA + i * 16, kk * 2 + chA));
#pragma unroll
                for (int j = 0; j < 4; j++) MMA_BF16(acc[i][j], al4, bb[j]);
            }
            // B lo (overwrite bb)
#pragma unroll
            for (int p = 0; p < 2; p++) {
                uint32_t t4[4];
                LDSM4(t4, stc + 24576u + swz(rowB + p * 16, kk * 2 + chB));
                bb[p * 2][0] = t4[0]; bb[p * 2][1] = t4[1];
                bb[p * 2 + 1][0] = t4[2]; bb[p * 2 + 1][1] = t4[3];
            }
#pragma unroll
            for (int i = 0; i < 4; i++)
#pragma unroll
                for (int j = 0; j < 4; j++) MMA_BF16(acc[i][j], ah[i], bb[j]);
        }

        if (c + 2 < NC) issue(c + 2, st_fill);
        CP_COMMIT();                                  // commit (possibly empty)
        st_cur  = (st_cur  == 65536u) ? 0u : st_cur  + 32768u;
        st_fill = (st_fill == 65536u) ? 0u : st_fill + 32768u;
    }

    // ---- epilogue ----
    const int qr = lane >> 2;
    const int qc = (lane & 3) * 2;
#pragma unroll
    for (int i = 0; i < 4; i++) {
#pragma unroll
        for (int h = 0; h < 2; h++) {
            const int grow = row0 + wm * 64 + i * 16 + qr + h * 8;
            if (grow >= cnt) continue;
#pragma unroll
            for (int j = 0; j < 4; j++) {
                const int col = col0 + wn * 32 + j * 8 + qc;
                float v0 = acc[i][j][h * 2 + 0] + bias[(size_t)e * NTOT + col];
                float v1 = acc[i][j][h * 2 + 1] + bias[(size_t)e * NTOT + col + 1];
                if (WRITE_H) {
                    v0 = 0.5f * v0 * (1.0f + erff(v0 * 0.70710678118654752f));
                    v1 = 0.5f * v1 * (1.0f + erff(v1 * 0.70710678118654752f));
                    uint32_t hi, lo;
                    split2(v0, v1, hi, lo);
                    size_t o = (size_t)(base + grow) * NTOT + col;
                    *(uint32_t*)(Hhi + o) = hi;
                    *(uint32_t*)(Hlo + o) = lo;
                } else {
                    size_t orow = SCATTER_OUT ? (size_t)g_tok[base + grow]
                                              : (size_t)(base + grow);
                    *(float2*)(OutF + orow * NTOT + col) = make_float2(v0, v1);
                }
            }
        }
    }
}

// ------------------------- launch --------------------------------------------
extern "C" void kernel_launch(void* const* d_in, const int* in_sizes, int n_in,
                              void* d_out, int out_size) {
    const float* x  = (const float*)d_in[0];
    const float* Wr = (const float*)d_in[1];
    const float* br = (const float*)d_in[2];
    const float* W1 = (const float*)d_in[3];
    const float* b1 = (const float*)d_in[4];
    const float* W2 = (const float*)d_in[5];
    const float* b2 = (const float*)d_in[6];
    float* out = (float*)d_out;

    __nv_bfloat16 *xh, *xl, *hh, *hl, *w1h, *w1l, *w2h, *w2l;
    cudaGetSymbolAddress((void**)&xh,  g_xh);
    cudaGetSymbolAddress((void**)&xl,  g_xl);
    cudaGetSymbolAddress((void**)&hh,  g_hh);
    cudaGetSymbolAddress((void**)&hl,  g_hl);
    cudaGetSymbolAddress((void**)&w1h, g_w1h);
    cudaGetSymbolAddress((void**)&w1l, g_w1l);
    cudaGetSymbolAddress((void**)&w2h, g_w2h);
    cudaGetSymbolAddress((void**)&w2l, g_w2l);

    const int SMEM_DYN = 3 * 32768;
    cudaFuncSetAttribute((const void*)k_mma<DIM, HID, true,  false>,
                         cudaFuncAttributeMaxDynamicSharedMemorySize, SMEM_DYN);
    cudaFuncSetAttribute((const void*)k_mma<HID, DIM, false, true>,
                         cudaFuncAttributeMaxDynamicSharedMemorySize, SMEM_DYN);

    k_init<<<1, 32>>>();
    k_router<<<TOK / 8, 256>>>(x, Wr, br);
    k_scan<<<1, 32>>>();
    k_scatter<<<TOK / 256, 256>>>();
    k_gsplit<<<TOK, 256>>>(x);
    k_tsplit<<<dim3(HID / 32, DIM / 32, NEXP), dim3(32, 8)>>>(W1, w1h, w1l, DIM, HID);
    k_tsplit<<<dim3(DIM / 32, HID / 32, NEXP), dim3(32, 8)>>>(W2, w2h, w2l, HID, DIM);

    k_mma<DIM, HID, true,  false>
        <<<dim3(HID / 128, TOK / 128, NEXP), 256, SMEM_DYN>>>(
            xh, xl, w1h, w1l, b1, nullptr, hh, hl);
    k_mma<HID, DIM, false, true>
        <<<dim3(DIM / 128, TOK / 128, NEXP), 256, SMEM_DYN>>>(
            hh, hl, w2h, w2l, b2, out, nullptr, nullptr);
}

// round 7
// speedup vs baseline: 3.8035x; 1.5004x over previous
#include <cuda_runtime.h>
#include <cuda_fp16.h>
#include <math.h>
#include <stdint.h>

#define TOK   8192
#define DIM   1024
#define NEXP  8
#define HID   4096
#define PAD   128

// ------------------------- device scratch (no cudaMalloc) -------------------
__device__ int g_expert[TOK];
__device__ int g_counts[NEXP];
__device__ int g_offsets[NEXP];
__device__ int g_cursor[NEXP];
__device__ int g_tok[TOK];
// activations: single fp16 (zero-initialized; pad rows stay 0)
__device__ __half g_xa [(size_t)(TOK + PAD) * DIM];
__device__ __half g_ha [(size_t)(TOK + PAD) * HID];
// weights: fp16 hi/lo transposed
__device__ __half g_w1h[(size_t)NEXP * DIM * HID];   // [e][h][d]
__device__ __half g_w1l[(size_t)NEXP * DIM * HID];
__device__ __half g_w2h[(size_t)NEXP * DIM * HID];   // [e][d][h]
__device__ __half g_w2l[(size_t)NEXP * DIM * HID];

// ------------------------- helpers ------------------------------------------
__device__ __forceinline__ uint32_t smem_u32(const void* p) {
    uint32_t a;
    asm("{ .reg .u64 t; cvta.to.shared.u64 t, %1; cvt.u32.u64 %0, t; }" : "=r"(a) : "l"(p));
    return a;
}
#define LDSM4(r, addr)                                                          \
    asm volatile("ldmatrix.sync.aligned.m8n8.x4.shared.b16 {%0,%1,%2,%3}, [%4];" \
        : "=r"((r)[0]), "=r"((r)[1]), "=r"((r)[2]), "=r"((r)[3]) : "r"(addr))
#define MMA_F16(d, a, b)                                                        \
    asm volatile("mma.sync.aligned.m16n8k16.row.col.f32.f16.f16.f32 "           \
        "{%0,%1,%2,%3},{%4,%5,%6,%7},{%8,%9},{%0,%1,%2,%3};"                    \
        : "+f"((d)[0]), "+f"((d)[1]), "+f"((d)[2]), "+f"((d)[3])                 \
        : "r"((a)[0]), "r"((a)[1]), "r"((a)[2]), "r"((a)[3]),                    \
          "r"((b)[0]), "r"((b)[1]))
#define CP16(dst, src)                                                          \
    asm volatile("cp.async.cg.shared.global [%0], [%1], 16;" :: "r"(dst), "l"(src) : "memory")
#define CP_COMMIT() asm volatile("cp.async.commit_group;" ::: "memory")
#define CP_WAIT1()  asm volatile("cp.async.wait_group 1;"  ::: "memory")

// swizzled byte offset of 16B chunk within a 128x32-fp16 tile (64B rows)
__device__ __forceinline__ uint32_t swz(uint32_t row, uint32_t chunk) {
    return row * 64u + (((chunk ^ (row >> 1)) & 3u) << 4);
}

// ------------------------- small kernels ------------------------------------
__global__ void k_init() {
    int i = threadIdx.x;
    if (i < NEXP) { g_counts[i] = 0; g_cursor[i] = 0; }
}

__global__ void k_router(const float* __restrict__ x,
                         const float* __restrict__ Wr,
                         const float* __restrict__ br) {
    int warp = (blockIdx.x * blockDim.x + threadIdx.x) >> 5;
    int lane = threadIdx.x & 31;
    if (warp >= TOK) return;
    float acc[NEXP];
#pragma unroll
    for (int e = 0; e < NEXP; e++) acc[e] = 0.f;
    const float* xr = x + (size_t)warp * DIM;
    for (int d = lane; d < DIM; d += 32) {
        float xv = xr[d];
        float4 w0 = *(const float4*)(Wr + (size_t)d * NEXP);
        float4 w1 = *(const float4*)(Wr + (size_t)d * NEXP + 4);
        acc[0] += xv * w0.x; acc[1] += xv * w0.y; acc[2] += xv * w0.z; acc[3] += xv * w0.w;
        acc[4] += xv * w1.x; acc[5] += xv * w1.y; acc[6] += xv * w1.z; acc[7] += xv * w1.w;
    }
#pragma unroll
    for (int e = 0; e < NEXP; e++)
#pragma unroll
        for (int off = 16; off > 0; off >>= 1)
            acc[e] += __shfl_xor_sync(0xFFFFFFFFu, acc[e], off);
    if (lane == 0) {
        float best = acc[0] + br[0]; int bi = 0;
#pragma unroll
        for (int e = 1; e < NEXP; e++) {
            float v = acc[e] + br[e];
            if (v > best) { best = v; bi = e; }
        }
        g_expert[warp] = bi;
        atomicAdd(&g_counts[bi], 1);
    }
}

__global__ void k_scan() {
    if (threadIdx.x == 0) {
        int s = 0;
        for (int e = 0; e < NEXP; e++) { g_offsets[e] = s; s += g_counts[e]; }
    }
}

__global__ void k_scatter() {
    int t = blockIdx.x * blockDim.x + threadIdx.x;
    if (t >= TOK) return;
    int e = g_expert[t];
    g_tok[g_offsets[e] + atomicAdd(&g_cursor[e], 1)] = t;
}

// gather x rows into permuted fp16 buffer
__global__ void k_gather16(const float* __restrict__ x) {
    int pos = blockIdx.x;
    int t = g_tok[pos];
    float4 v = ((const float4*)(x + (size_t)t * DIM))[threadIdx.x];
    __half2 p0 = __floats2half2_rn(v.x, v.y);
    __half2 p1 = __floats2half2_rn(v.z, v.w);
    *(__half2*)(g_xa + (size_t)pos * DIM + threadIdx.x * 4)     = p0;
    *(__half2*)(g_xa + (size_t)pos * DIM + threadIdx.x * 4 + 2) = p1;
}

// transpose + fp16 hi/lo split per expert: src [E][R][C] fp32 -> dst [E][C][R]
__global__ void k_tsplit(const float* __restrict__ src,
                         __half* __restrict__ dhi,
                         __half* __restrict__ dlo, int R, int C) {
    __shared__ float tile[32][33];
    const float* s = src + (size_t)blockIdx.z * R * C;
    size_t dbase = (size_t)blockIdx.z * R * C;
    int c0 = blockIdx.x * 32, r0 = blockIdx.y * 32;
#pragma unroll
    for (int i = threadIdx.y; i < 32; i += 8)
        tile[i][threadIdx.x] = s[(size_t)(r0 + i) * C + c0 + threadIdx.x];
    __syncthreads();
#pragma unroll
    for (int i = threadIdx.y; i < 32; i += 8) {
        float v = tile[threadIdx.x][i];
        __half h = __float2half(v);
        __half l = __float2half(v - __half2float(h));
        size_t o = dbase + (size_t)(c0 + i) * R + r0 + threadIdx.x;
        dhi[o] = h;
        dlo[o] = l;
    }
}

// ------------------------- fp16x2 HMMA grouped GEMM --------------------------
// D = A*(Bh+Bl); A single fp16, B split fp16 hi/lo -> 2 MMA products.
// 128x128 CTA tile, BK=32, 3-stage cp.async pipeline (24KB/stage).
// Iter c computes stage c%3, refills stage (c+2)%3.
template<int KTOT, int NTOT, bool WRITE_H, bool SCATTER_OUT>
__global__ __launch_bounds__(256, 2)
void k_mma(const __half* __restrict__ A,
           const __half* __restrict__ Bhi, const __half* __restrict__ Blo,
           const float* __restrict__ bias, float* __restrict__ OutF,
           __half* __restrict__ Hout) {
    extern __shared__ char smem[];
    const int e    = blockIdx.z;
    const int cnt  = g_counts[e];
    const int row0 = blockIdx.y * 128;
    if (row0 >= cnt) return;
    const int base = g_offsets[e];
    const int col0 = blockIdx.x * 128;

    const uint32_t sb = smem_u32(smem);
    const int tid  = threadIdx.x;
    const int lane = tid & 31, warp = tid >> 5;
    const int wm = warp & 1, wn = warp >> 1;        // 2 x 4 warp grid

    // ---- producer: thread -> (row = tid/2, 32B half = tid&1); predicate-free
    const int pr = tid >> 1;
    const int hf = tid & 1;
    const size_t arow = (size_t)(base + row0 + pr);          // < TOK+PAD
    const size_t brow = (size_t)e * NTOT + col0 + pr;
    const __half* pA   = A   + arow * KTOT + hf * 16;
    const __half* pB_h = Bhi + brow * KTOT + hf * 16;
    const __half* pB_l = Blo + brow * KTOT + hf * 16;
    const uint32_t d0 = swz((uint32_t)pr, (uint32_t)(hf * 2));
    const uint32_t d1 = swz((uint32_t)pr, (uint32_t)(hf * 2 + 1));

    const uint32_t STG = 24576u;  // stage stride: A(8K) + Bh(8K) + Bl(8K)
    auto issue = [&](int c, uint32_t stoff) {
        const size_t ko = (size_t)c * 32;
        const uint32_t s0 = sb + stoff;
        CP16(s0 + d0,          pA   + ko); CP16(s0 + d1,          pA   + ko + 8);
        CP16(s0 + 8192  + d0,  pB_h + ko); CP16(s0 + 8192  + d1,  pB_h + ko + 8);
        CP16(s0 + 16384 + d0,  pB_l + ko); CP16(s0 + 16384 + d1,  pB_l + ko + 8);
    };

    // ---- consumer (ldmatrix) mapping ----
    const uint32_t g  = (uint32_t)lane >> 3;
    const uint32_t lr = (uint32_t)lane & 7;
    const uint32_t rowA = (uint32_t)(wm * 64) + (g & 1) * 8 + lr;
    const uint32_t chA  = g >> 1;
    const uint32_t rowB = (uint32_t)(wn * 32) + (g >> 1) * 8 + lr;
    const uint32_t chB  = g & 1;

    float acc[4][4][4];
#pragma unroll
    for (int i = 0; i < 4; i++)
#pragma unroll
        for (int j = 0; j < 4; j++)
#pragma unroll
            for (int q = 0; q < 4; q++) acc[i][j][q] = 0.f;

    const int NC = KTOT / 32;
    issue(0, 0);      CP_COMMIT();
    issue(1, STG);    CP_COMMIT();

    uint32_t st_cur = 0, st_fill = 2 * STG;
    for (int c = 0; c < NC; c++) {
        CP_WAIT1();
        __syncthreads();

        const uint32_t stc = sb + st_cur;
#pragma unroll
        for (int kk = 0; kk < 2; kk++) {
            uint32_t ah[4][4], bb[4][2];
#pragma unroll
            for (int i = 0; i < 4; i++)
                LDSM4(ah[i], stc + swz(rowA + i * 16, kk * 2 + chA));
            // B hi
#pragma unroll
            for (int p = 0; p < 2; p++) {
                uint32_t t4[4];
                LDSM4(t4, stc + 8192u + swz(rowB + p * 16, kk * 2 + chB));
                bb[p * 2][0] = t4[0]; bb[p * 2][1] = t4[1];
                bb[p * 2 + 1][0] = t4[2]; bb[p * 2 + 1][1] = t4[3];
            }
#pragma unroll
            for (int i = 0; i < 4; i++)
#pragma unroll
                for (int j = 0; j < 4; j++) MMA_F16(acc[i][j], ah[i], bb[j]);
            // B lo (overwrite bb)
#pragma unroll
            for (int p = 0; p < 2; p++) {
                uint32_t t4[4];
                LDSM4(t4, stc + 16384u + swz(rowB + p * 16, kk * 2 + chB));
                bb[p * 2][0] = t4[0]; bb[p * 2][1] = t4[1];
                bb[p * 2 + 1][0] = t4[2]; bb[p * 2 + 1][1] = t4[3];
            }
#pragma unroll
            for (int i = 0; i < 4; i++)
#pragma unroll
                for (int j = 0; j < 4; j++) MMA_F16(acc[i][j], ah[i], bb[j]);
        }

        if (c + 2 < NC) issue(c + 2, st_fill);
        CP_COMMIT();
        st_cur  = (st_cur  == 2 * STG) ? 0u : st_cur  + STG;
        st_fill = (st_fill == 2 * STG) ? 0u : st_fill + STG;
    }

    // ---- epilogue ----
    const int qr = lane >> 2;
    const int qc = (lane & 3) * 2;
#pragma unroll
    for (int i = 0; i < 4; i++) {
#pragma unroll
        for (int h = 0; h < 2; h++) {
            const int grow = row0 + wm * 64 + i * 16 + qr + h * 8;
            if (grow >= cnt) continue;
#pragma unroll
            for (int j = 0; j < 4; j++) {
                const int col = col0 + wn * 32 + j * 8 + qc;
                float v0 = acc[i][j][h * 2 + 0] + bias[(size_t)e * NTOT + col];
                float v1 = acc[i][j][h * 2 + 1] + bias[(size_t)e * NTOT + col + 1];
                if (WRITE_H) {
                    v0 = 0.5f * v0 * (1.0f + erff(v0 * 0.70710678118654752f));
                    v1 = 0.5f * v1 * (1.0f + erff(v1 * 0.70710678118654752f));
                    *(__half2*)(Hout + (size_t)(base + grow) * NTOT + col) =
                        __floats2half2_rn(v0, v1);
                } else {
                    size_t orow = SCATTER_OUT ? (size_t)g_tok[base + grow]
                                              : (size_t)(base + grow);
                    *(float2*)(OutF + orow * NTOT + col) = make_float2(v0, v1);
                }
            }
        }
    }
}

// ------------------------- launch --------------------------------------------
extern "C" void kernel_launch(void* const* d_in, const int* in_sizes, int n_in,
                              void* d_out, int out_size) {
    const float* x  = (const float*)d_in[0];
    const float* Wr = (const float*)d_in[1];
    const float* br = (const float*)d_in[2];
    const float* W1 = (const float*)d_in[3];
    const float* b1 = (const float*)d_in[4];
    const float* W2 = (const float*)d_in[5];
    const float* b2 = (const float*)d_in[6];
    float* out = (float*)d_out;

    __half *xa, *ha, *w1h, *w1l, *w2h, *w2l;
    cudaGetSymbolAddress((void**)&xa,  g_xa);
    cudaGetSymbolAddress((void**)&ha,  g_ha);
    cudaGetSymbolAddress((void**)&w1h, g_w1h);
    cudaGetSymbolAddress((void**)&w1l, g_w1l);
    cudaGetSymbolAddress((void**)&w2h, g_w2h);
    cudaGetSymbolAddress((void**)&w2l, g_w2l);

    const int SMEM_DYN = 3 * 24576;
    cudaFuncSetAttribute((const void*)k_mma<DIM, HID, true,  false>,
                         cudaFuncAttributeMaxDynamicSharedMemorySize, SMEM_DYN);
    cudaFuncSetAttribute((const void*)k_mma<HID, DIM, false, true>,
                         cudaFuncAttributeMaxDynamicSharedMemorySize, SMEM_DYN);

    k_init<<<1, 32>>>();
    k_router<<<TOK / 8, 256>>>(x, Wr, br);
    k_scan<<<1, 32>>>();
    k_scatter<<<TOK / 256, 256>>>();
    k_gather16<<<TOK, 256>>>(x);
    k_tsplit<<<dim3(HID / 32, DIM / 32, NEXP), dim3(32, 8)>>>(W1, w1h, w1l, DIM, HID);
    k_tsplit<<<dim3(DIM / 32, HID / 32, NEXP), dim3(32, 8)>>>(W2, w2h, w2l, HID, DIM);

    k_mma<DIM, HID, true,  false>
        <<<dim3(HID / 128, TOK / 128, NEXP), 256, SMEM_DYN>>>(
            xa, w1h, w1l, b1, nullptr, ha);
    k_mma<HID, DIM, false, true>
        <<<dim3(DIM / 128, TOK / 128, NEXP), 256, SMEM_DYN>>>(
            ha, w2h, w2l, b2, out, nullptr);
}

// round 8
// speedup vs baseline: 5.3773x; 1.4138x over previous
#include <cuda_runtime.h>
#include <cuda_fp16.h>
#include <math.h>
#include <stdint.h>

#define TOK   8192
#define DIM   1024
#define NEXP  8
#define HID   4096
#define PAD   128

// ------------------------- device scratch (no cudaMalloc) -------------------
__device__ int g_expert[TOK];
__device__ int g_counts[NEXP];
__device__ int g_offsets[NEXP];
__device__ int g_cursor[NEXP];
__device__ int g_tok[TOK];
// activations: fp16 (zero-initialized; pad rows stay 0)
__device__ __half g_xa[(size_t)(TOK + PAD) * DIM];
__device__ __half g_ha[(size_t)(TOK + PAD) * HID];
// weights: fp16, transposed
__device__ __half g_w1t[(size_t)NEXP * DIM * HID];   // [e][h][d]
__device__ __half g_w2t[(size_t)NEXP * DIM * HID];   // [e][d][h]

// ------------------------- helpers ------------------------------------------
__device__ __forceinline__ uint32_t smem_u32(const void* p) {
    uint32_t a;
    asm("{ .reg .u64 t; cvta.to.shared.u64 t, %1; cvt.u32.u64 %0, t; }" : "=r"(a) : "l"(p));
    return a;
}
#define LDSM4(r, addr)                                                          \
    asm volatile("ldmatrix.sync.aligned.m8n8.x4.shared.b16 {%0,%1,%2,%3}, [%4];" \
        : "=r"((r)[0]), "=r"((r)[1]), "=r"((r)[2]), "=r"((r)[3]) : "r"(addr))
#define MMA_F16(d, a, b)                                                        \
    asm volatile("mma.sync.aligned.m16n8k16.row.col.f32.f16.f16.f32 "           \
        "{%0,%1,%2,%3},{%4,%5,%6,%7},{%8,%9},{%0,%1,%2,%3};"                    \
        : "+f"((d)[0]), "+f"((d)[1]), "+f"((d)[2]), "+f"((d)[3])                 \
        : "r"((a)[0]), "r"((a)[1]), "r"((a)[2]), "r"((a)[3]),                    \
          "r"((b)[0]), "r"((b)[1]))
#define CP16(dst, src)                                                          \
    asm volatile("cp.async.cg.shared.global [%0], [%1], 16;" :: "r"(dst), "l"(src) : "memory")
#define CP_COMMIT() asm volatile("cp.async.commit_group;" ::: "memory")
#define CP_WAIT1()  asm volatile("cp.async.wait_group 1;"  ::: "memory")

// swizzled byte offset of 16B chunk within a 128x32-fp16 tile (64B rows)
__device__ __forceinline__ uint32_t swz(uint32_t row, uint32_t chunk) {
    return row * 64u + (((chunk ^ (row >> 1)) & 3u) << 4);
}

// ------------------------- small kernels ------------------------------------
__global__ void k_init() {
    int i = threadIdx.x;
    if (i < NEXP) { g_counts[i] = 0; g_cursor[i] = 0; }
}

__global__ void k_router(const float* __restrict__ x,
                         const float* __restrict__ Wr,
                         const float* __restrict__ br) {
    int warp = (blockIdx.x * blockDim.x + threadIdx.x) >> 5;
    int lane = threadIdx.x & 31;
    if (warp >= TOK) return;
    float acc[NEXP];
#pragma unroll
    for (int e = 0; e < NEXP; e++) acc[e] = 0.f;
    const float* xr = x + (size_t)warp * DIM;
    for (int d = lane; d < DIM; d += 32) {
        float xv = xr[d];
        float4 w0 = *(const float4*)(Wr + (size_t)d * NEXP);
        float4 w1 = *(const float4*)(Wr + (size_t)d * NEXP + 4);
        acc[0] += xv * w0.x; acc[1] += xv * w0.y; acc[2] += xv * w0.z; acc[3] += xv * w0.w;
        acc[4] += xv * w1.x; acc[5] += xv * w1.y; acc[6] += xv * w1.z; acc[7] += xv * w1.w;
    }
#pragma unroll
    for (int e = 0; e < NEXP; e++)
#pragma unroll
        for (int off = 16; off > 0; off >>= 1)
            acc[e] += __shfl_xor_sync(0xFFFFFFFFu, acc[e], off);
    if (lane == 0) {
        float best = acc[0] + br[0]; int bi = 0;
#pragma unroll
        for (int e = 1; e < NEXP; e++) {
            float v = acc[e] + br[e];
            if (v > best) { best = v; bi = e; }
        }
        g_expert[warp] = bi;
        atomicAdd(&g_counts[bi], 1);
    }
}

__global__ void k_scan() {
    if (threadIdx.x == 0) {
        int s = 0;
        for (int e = 0; e < NEXP; e++) { g_offsets[e] = s; s += g_counts[e]; }
    }
}

__global__ void k_scatter() {
    int t = blockIdx.x * blockDim.x + threadIdx.x;
    if (t >= TOK) return;
    int e = g_expert[t];
    g_tok[g_offsets[e] + atomicAdd(&g_cursor[e], 1)] = t;
}

// gather x rows into permuted fp16 buffer
__global__ void k_gather16(const float* __restrict__ x) {
    int pos = blockIdx.x;
    int t = g_tok[pos];
    float4 v = ((const float4*)(x + (size_t)t * DIM))[threadIdx.x];
    *(__half2*)(g_xa + (size_t)pos * DIM + threadIdx.x * 4)     = __floats2half2_rn(v.x, v.y);
    *(__half2*)(g_xa + (size_t)pos * DIM + threadIdx.x * 4 + 2) = __floats2half2_rn(v.z, v.w);
}

// transpose + fp16 convert per expert: src [E][R][C] fp32 -> dst [E][C][R] fp16
__global__ void k_tconv(const float* __restrict__ src,
                        __half* __restrict__ dst, int R, int C) {
    __shared__ float tile[32][33];
    const float* s = src + (size_t)blockIdx.z * R * C;
    size_t dbase = (size_t)blockIdx.z * R * C;
    int c0 = blockIdx.x * 32, r0 = blockIdx.y * 32;
#pragma unroll
    for (int i = threadIdx.y; i < 32; i += 8)
        tile[i][threadIdx.x] = s[(size_t)(r0 + i) * C + c0 + threadIdx.x];
    __syncthreads();
#pragma unroll
    for (int i = threadIdx.y; i < 32; i += 8)
        dst[dbase + (size_t)(c0 + i) * R + r0 + threadIdx.x] =
            __float2half(tile[threadIdx.x][i]);
}

// ------------------------- fp16 HMMA grouped GEMM ----------------------------
// D = A*B, both plain fp16 (1 product). 128x128 CTA tile, BK=32,
// 3-stage cp.async pipeline (16KB/stage). Iter c computes stage c%3,
// refills stage (c+2)%3.
template<int KTOT, int NTOT, bool WRITE_H, bool SCATTER_OUT>
__global__ __launch_bounds__(256, 2)
void k_mma(const __half* __restrict__ A, const __half* __restrict__ B,
           const float* __restrict__ bias, float* __restrict__ OutF,
           __half* __restrict__ Hout) {
    extern __shared__ char smem[];
    const int e    = blockIdx.z;
    const int cnt  = g_counts[e];
    const int row0 = blockIdx.y * 128;
    if (row0 >= cnt) return;
    const int base = g_offsets[e];
    const int col0 = blockIdx.x * 128;

    const uint32_t sb = smem_u32(smem);
    const int tid  = threadIdx.x;
    const int lane = tid & 31, warp = tid >> 5;
    const int wm = warp & 1, wn = warp >> 1;        // 2 x 4 warp grid

    // ---- producer: thread -> (row = tid/2, 32B half = tid&1); predicate-free
    const int pr = tid >> 1;
    const int hf = tid & 1;
    const size_t arow = (size_t)(base + row0 + pr);          // < TOK+PAD
    const size_t brow = (size_t)e * NTOT + col0 + pr;
    const __half* pA = A + arow * KTOT + hf * 16;
    const __half* pB = B + brow * KTOT + hf * 16;
    const uint32_t d0 = swz((uint32_t)pr, (uint32_t)(hf * 2));
    const uint32_t d1 = swz((uint32_t)pr, (uint32_t)(hf * 2 + 1));

    const uint32_t STG = 16384u;  // stage stride: A(8K) + B(8K)
    auto issue = [&](int c, uint32_t stoff) {
        const size_t ko = (size_t)c * 32;
        const uint32_t s0 = sb + stoff;
        CP16(s0 + d0,         pA + ko); CP16(s0 + d1,         pA + ko + 8);
        CP16(s0 + 8192 + d0,  pB + ko); CP16(s0 + 8192 + d1,  pB + ko + 8);
    };

    // ---- consumer (ldmatrix) mapping ----
    const uint32_t g  = (uint32_t)lane >> 3;
    const uint32_t lr = (uint32_t)lane & 7;
    const uint32_t rowA = (uint32_t)(wm * 64) + (g & 1) * 8 + lr;
    const uint32_t chA  = g >> 1;
    const uint32_t rowB = (uint32_t)(wn * 32) + (g >> 1) * 8 + lr;
    const uint32_t chB  = g & 1;

    float acc[4][4][4];
#pragma unroll
    for (int i = 0; i < 4; i++)
#pragma unroll
        for (int j = 0; j < 4; j++)
#pragma unroll
            for (int q = 0; q < 4; q++) acc[i][j][q] = 0.f;

    const int NC = KTOT / 32;
    issue(0, 0);      CP_COMMIT();
    issue(1, STG);    CP_COMMIT();

    uint32_t st_cur = 0, st_fill = 2 * STG;
    for (int c = 0; c < NC; c++) {
        CP_WAIT1();
        __syncthreads();

        const uint32_t stc = sb + st_cur;
#pragma unroll
        for (int kk = 0; kk < 2; kk++) {
            uint32_t ah[4][4], bb[4][2];
#pragma unroll
            for (int i = 0; i < 4; i++)
                LDSM4(ah[i], stc + swz(rowA + i * 16, kk * 2 + chA));
#pragma unroll
            for (int p = 0; p < 2; p++) {
                uint32_t t4[4];
                LDSM4(t4, stc + 8192u + swz(rowB + p * 16, kk * 2 + chB));
                bb[p * 2][0] = t4[0]; bb[p * 2][1] = t4[1];
                bb[p * 2 + 1][0] = t4[2]; bb[p * 2 + 1][1] = t4[3];
            }
#pragma unroll
            for (int i = 0; i < 4; i++)
#pragma unroll
                for (int j = 0; j < 4; j++) MMA_F16(acc[i][j], ah[i], bb[j]);
        }

        if (c + 2 < NC) issue(c + 2, st_fill);
        CP_COMMIT();
        st_cur  = (st_cur  == 2 * STG) ? 0u : st_cur  + STG;
        st_fill = (st_fill == 2 * STG) ? 0u : st_fill + STG;
    }

    // ---- epilogue ----
    const int qr = lane >> 2;
    const int qc = (lane & 3) * 2;
#pragma unroll
    for (int i = 0; i < 4; i++) {
#pragma unroll
        for (int h = 0; h < 2; h++) {
            const int grow = row0 + wm * 64 + i * 16 + qr + h * 8;
            if (grow >= cnt) continue;
#pragma unroll
            for (int j = 0; j < 4; j++) {
                const int col = col0 + wn * 32 + j * 8 + qc;
                float v0 = acc[i][j][h * 2 + 0] + bias[(size_t)e * NTOT + col];
                float v1 = acc[i][j][h * 2 + 1] + bias[(size_t)e * NTOT + col + 1];
                if (WRITE_H) {
                    v0 = 0.5f * v0 * (1.0f + erff(v0 * 0.70710678118654752f));
                    v1 = 0.5f * v1 * (1.0f + erff(v1 * 0.70710678118654752f));
                    *(__half2*)(Hout + (size_t)(base + grow) * NTOT + col) =
                        __floats2half2_rn(v0, v1);
                } else {
                    size_t orow = SCATTER_OUT ? (size_t)g_tok[base + grow]
                                              : (size_t)(base + grow);
                    *(float2*)(OutF + orow * NTOT + col) = make_float2(v0, v1);
                }
            }
        }
    }
}

// ------------------------- launch --------------------------------------------
extern "C" void kernel_launch(void* const* d_in, const int* in_sizes, int n_in,
                              void* d_out, int out_size) {
    const float* x  = (const float*)d_in[0];
    const float* Wr = (const float*)d_in[1];
    const float* br = (const float*)d_in[2];
    const float* W1 = (const float*)d_in[3];
    const float* b1 = (const float*)d_in[4];
    const float* W2 = (const float*)d_in[5];
    const float* b2 = (const float*)d_in[6];
    float* out = (float*)d_out;

    __half *xa, *ha, *w1t, *w2t;
    cudaGetSymbolAddress((void**)&xa,  g_xa);
    cudaGetSymbolAddress((void**)&ha,  g_ha);
    cudaGetSymbolAddress((void**)&w1t, g_w1t);
    cudaGetSymbolAddress((void**)&w2t, g_w2t);

    const int SMEM_DYN = 3 * 16384;
    cudaFuncSetAttribute((const void*)k_mma<DIM, HID, true,  false>,
                         cudaFuncAttributeMaxDynamicSharedMemorySize, SMEM_DYN);
    cudaFuncSetAttribute((const void*)k_mma<HID, DIM, false, true>,
                         cudaFuncAttributeMaxDynamicSharedMemorySize, SMEM_DYN);

    k_init<<<1, 32>>>();
    k_router<<<TOK / 8, 256>>>(x, Wr, br);
    k_scan<<<1, 32>>>();
    k_scatter<<<TOK / 256, 256>>>();
    k_gather16<<<TOK, 256>>>(x);
    k_tconv<<<dim3(HID / 32, DIM / 32, NEXP), dim3(32, 8)>>>(W1, w1t, DIM, HID);
    k_tconv<<<dim3(DIM / 32, HID / 32, NEXP), dim3(32, 8)>>>(W2, w2t, HID, DIM);

    k_mma<DIM, HID, true,  false>
        <<<dim3(HID / 128, TOK / 128, NEXP), 256, SMEM_DYN>>>(xa, w1t, b1, nullptr, ha);
    k_mma<HID, DIM, false, true>
        <<<dim3(DIM / 128, TOK / 128, NEXP), 256, SMEM_DYN>>>(ha, w2t, b2, out, nullptr);
}

// round 9
// speedup vs baseline: 5.3827x; 1.0010x over previous
#include <cuda_runtime.h>
#include <cuda_fp16.h>
#include <math.h>
#include <stdint.h>

#define TOK   8192
#define DIM   1024
#define NEXP  8
#define HID   4096
#define PAD   128

// ------------------------- device scratch (no cudaMalloc) -------------------
__device__ int g_expert[TOK];
__device__ int g_counts[NEXP];
__device__ int g_offsets[NEXP];
__device__ int g_cursor[NEXP];
__device__ int g_tok[TOK];
// activations: fp16 (zero-initialized; pad rows stay 0)
__device__ __half g_xa[(size_t)(TOK + PAD) * DIM];
__device__ __half g_ha[(size_t)(TOK + PAD) * HID];
// weights: fp16, transposed
__device__ __half g_w1t[(size_t)NEXP * DIM * HID];   // [e][h][d]
__device__ __half g_w2t[(size_t)NEXP * DIM * HID];   // [e][d][h]

// ------------------------- helpers ------------------------------------------
__device__ __forceinline__ uint32_t smem_u32(const void* p) {
    uint32_t a;
    asm("{ .reg .u64 t; cvta.to.shared.u64 t, %1; cvt.u32.u64 %0, t; }" : "=r"(a) : "l"(p));
    return a;
}
#define LDSM4(r, addr)                                                          \
    asm volatile("ldmatrix.sync.aligned.m8n8.x4.shared.b16 {%0,%1,%2,%3}, [%4];" \
        : "=r"((r)[0]), "=r"((r)[1]), "=r"((r)[2]), "=r"((r)[3]) : "r"(addr))
#define MMA_F16(d, a, b)                                                        \
    asm volatile("mma.sync.aligned.m16n8k16.row.col.f32.f16.f16.f32 "           \
        "{%0,%1,%2,%3},{%4,%5,%6,%7},{%8,%9},{%0,%1,%2,%3};"                    \
        : "+f"((d)[0]), "+f"((d)[1]), "+f"((d)[2]), "+f"((d)[3])                 \
        : "r"((a)[0]), "r"((a)[1]), "r"((a)[2]), "r"((a)[3]),                    \
          "r"((b)[0]), "r"((b)[1]))
#define CP16(dst, src)                                                          \
    asm volatile("cp.async.cg.shared.global [%0], [%1], 16;" :: "r"(dst), "l"(src) : "memory")
#define CP_COMMIT() asm volatile("cp.async.commit_group;" ::: "memory")
#define CP_WAIT1()  asm volatile("cp.async.wait_group 1;"  ::: "memory")

// swizzled byte offset of 16B chunk within a 128x32-fp16 tile (64B rows)
__device__ __forceinline__ uint32_t swz(uint32_t row, uint32_t chunk) {
    return row * 64u + (((chunk ^ (row >> 1)) & 3u) << 4);
}

// ------------------------- small kernels ------------------------------------
__global__ void k_init() {
    int i = threadIdx.x;
    if (i < NEXP) { g_counts[i] = 0; g_cursor[i] = 0; }
}

__global__ void k_router(const float* __restrict__ x,
                         const float* __restrict__ Wr,
                         const float* __restrict__ br) {
    int warp = (blockIdx.x * blockDim.x + threadIdx.x) >> 5;
    int lane = threadIdx.x & 31;
    if (warp >= TOK) return;
    float acc[NEXP];
#pragma unroll
    for (int e = 0; e < NEXP; e++) acc[e] = 0.f;
    const float* xr = x + (size_t)warp * DIM;
    for (int d = lane; d < DIM; d += 32) {
        float xv = xr[d];
        float4 w0 = *(const float4*)(Wr + (size_t)d * NEXP);
        float4 w1 = *(const float4*)(Wr + (size_t)d * NEXP + 4);
        acc[0] += xv * w0.x; acc[1] += xv * w0.y; acc[2] += xv * w0.z; acc[3] += xv * w0.w;
        acc[4] += xv * w1.x; acc[5] += xv * w1.y; acc[6] += xv * w1.z; acc[7] += xv * w1.w;
    }
#pragma unroll
    for (int e = 0; e < NEXP; e++)
#pragma unroll
        for (int off = 16; off > 0; off >>= 1)
            acc[e] += __shfl_xor_sync(0xFFFFFFFFu, acc[e], off);
    if (lane == 0) {
        float best = acc[0] + br[0]; int bi = 0;
#pragma unroll
        for (int e = 1; e < NEXP; e++) {
            float v = acc[e] + br[e];
            if (v > best) { best = v; bi = e; }
        }
        g_expert[warp] = bi;
        atomicAdd(&g_counts[bi], 1);
    }
}

__global__ void k_scan() {
    if (threadIdx.x == 0) {
        int s = 0;
        for (int e = 0; e < NEXP; e++) { g_offsets[e] = s; s += g_counts[e]; }
    }
}

__global__ void k_scatter() {
    int t = blockIdx.x * blockDim.x + threadIdx.x;
    if (t >= TOK) return;
    int e = g_expert[t];
    g_tok[g_offsets[e] + atomicAdd(&g_cursor[e], 1)] = t;
}

// gather x rows into permuted fp16 buffer
__global__ void k_gather16(const float* __restrict__ x) {
    int pos = blockIdx.x;
    int t = g_tok[pos];
    float4 v = ((const float4*)(x + (size_t)t * DIM))[threadIdx.x];
    *(__half2*)(g_xa + (size_t)pos * DIM + threadIdx.x * 4)     = __floats2half2_rn(v.x, v.y);
    *(__half2*)(g_xa + (size_t)pos * DIM + threadIdx.x * 4 + 2) = __floats2half2_rn(v.z, v.w);
}

// transpose + fp16 convert per expert: src [E][R][C] fp32 -> dst [E][C][R] fp16
__global__ void k_tconv(const float* __restrict__ src,
                        __half* __restrict__ dst, int R, int C) {
    __shared__ float tile[32][33];
    const float* s = src + (size_t)blockIdx.z * R * C;
    size_t dbase = (size_t)blockIdx.z * R * C;
    int c0 = blockIdx.x * 32, r0 = blockIdx.y * 32;
#pragma unroll
    for (int i = threadIdx.y; i < 32; i += 8)
        tile[i][threadIdx.x] = s[(size_t)(r0 + i) * C + c0 + threadIdx.x];
    __syncthreads();
#pragma unroll
    for (int i = threadIdx.y; i < 32; i += 8)
        dst[dbase + (size_t)(c0 + i) * R + r0 + threadIdx.x] =
            __float2half(tile[threadIdx.x][i]);
}

// ------------------------- fp16 HMMA grouped GEMM ----------------------------
// D = A*B, both fp16. 128x128 CTA tile, BK=32, 3-stage cp.async pipeline.
// Threadblock rasterization swizzle: consecutively-scheduled CTAs form
// 8-row x all-col bands so the concurrent L2 working set is ~8 A strips +
// the B strips of one band (~12MB) instead of ~296 distinct B strips (74MB).
template<int KTOT, int NTOT, bool WRITE_H, bool SCATTER_OUT>
__global__ __launch_bounds__(256, 2)
void k_mma(const __half* __restrict__ A, const __half* __restrict__ B,
           const float* __restrict__ bias, float* __restrict__ OutF,
           __half* __restrict__ Hout) {
    extern __shared__ char smem[];
    const int e   = blockIdx.z;
    const int cnt = g_counts[e];

    // ---- CTA swizzle: lin -> (rowt, colt) in 8-row bands, cols fastest ----
    const int lin      = blockIdx.y * gridDim.x + blockIdx.x;
    const int per_band = 8 * gridDim.x;                 // 8 rows x all cols
    const int band     = lin / per_band;
    const int rem      = lin - band * per_band;
    const int rowt     = band * 8 + (rem & 7);
    const int colt     = rem >> 3;

    const int row0 = rowt * 128;
    if (row0 >= cnt) return;
    const int base = g_offsets[e];
    const int col0 = colt * 128;

    const uint32_t sb = smem_u32(smem);
    const int tid  = threadIdx.x;
    const int lane = tid & 31, warp = tid >> 5;
    const int wm = warp & 1, wn = warp >> 1;        // 2 x 4 warp grid

    // ---- producer: thread -> (row = tid/2, 32B half = tid&1); predicate-free
    const int pr = tid >> 1;
    const int hf = tid & 1;
    const size_t arow = (size_t)(base + row0 + pr);          // < TOK+PAD
    const size_t brow = (size_t)e * NTOT + col0 + pr;
    const __half* pA = A + arow * KTOT + hf * 16;
    const __half* pB = B + brow * KTOT + hf * 16;
    const uint32_t d0 = swz((uint32_t)pr, (uint32_t)(hf * 2));
    const uint32_t d1 = swz((uint32_t)pr, (uint32_t)(hf * 2 + 1));

    const uint32_t STG = 16384u;  // stage stride: A(8K) + B(8K)
    auto issue = [&](int c, uint32_t stoff) {
        const size_t ko = (size_t)c * 32;
        const uint32_t s0 = sb + stoff;
        CP16(s0 + d0,         pA + ko); CP16(s0 + d1,         pA + ko + 8);
        CP16(s0 + 8192 + d0,  pB + ko); CP16(s0 + 8192 + d1,  pB + ko + 8);
    };

    // ---- consumer (ldmatrix) mapping ----
    const uint32_t g  = (uint32_t)lane >> 3;
    const uint32_t lr = (uint32_t)lane & 7;
    const uint32_t rowA = (uint32_t)(wm * 64) + (g & 1) * 8 + lr;
    const uint32_t chA  = g >> 1;
    const uint32_t rowB = (uint32_t)(wn * 32) + (g >> 1) * 8 + lr;
    const uint32_t chB  = g & 1;

    float acc[4][4][4];
#pragma unroll
    for (int i = 0; i < 4; i++)
#pragma unroll
        for (int j = 0; j < 4; j++)
#pragma unroll
            for (int q = 0; q < 4; q++) acc[i][j][q] = 0.f;

    const int NC = KTOT / 32;
    issue(0, 0);      CP_COMMIT();
    issue(1, STG);    CP_COMMIT();

    uint32_t st_cur = 0, st_fill = 2 * STG;
    for (int c = 0; c < NC; c++) {
        CP_WAIT1();
        __syncthreads();

        const uint32_t stc = sb + st_cur;
#pragma unroll
        for (int kk = 0; kk < 2; kk++) {
            uint32_t ah[4][4], bb[4][2];
#pragma unroll
            for (int i = 0; i < 4; i++)
                LDSM4(ah[i], stc + swz(rowA + i * 16, kk * 2 + chA));
#pragma unroll
            for (int p = 0; p < 2; p++) {
                uint32_t t4[4];
                LDSM4(t4, stc + 8192u + swz(rowB + p * 16, kk * 2 + chB));
                bb[p * 2][0] = t4[0]; bb[p * 2][1] = t4[1];
                bb[p * 2 + 1][0] = t4[2]; bb[p * 2 + 1][1] = t4[3];
            }
#pragma unroll
            for (int i = 0; i < 4; i++)
#pragma unroll
                for (int j = 0; j < 4; j++) MMA_F16(acc[i][j], ah[i], bb[j]);
        }

        if (c + 2 < NC) issue(c + 2, st_fill);
        CP_COMMIT();
        st_cur  = (st_cur  == 2 * STG) ? 0u : st_cur  + STG;
        st_fill = (st_fill == 2 * STG) ? 0u : st_fill + STG;
    }

    // ---- epilogue ----
    const int qr = lane >> 2;
    const int qc = (lane & 3) * 2;
#pragma unroll
    for (int i = 0; i < 4; i++) {
#pragma unroll
        for (int h = 0; h < 2; h++) {
            const int grow = row0 + wm * 64 + i * 16 + qr + h * 8;
            if (grow >= cnt) continue;
#pragma unroll
            for (int j = 0; j < 4; j++) {
                const int col = col0 + wn * 32 + j * 8 + qc;
                float v0 = acc[i][j][h * 2 + 0] + bias[(size_t)e * NTOT + col];
                float v1 = acc[i][j][h * 2 + 1] + bias[(size_t)e * NTOT + col + 1];
                if (WRITE_H) {
                    v0 = 0.5f * v0 * (1.0f + erff(v0 * 0.70710678118654752f));
                    v1 = 0.5f * v1 * (1.0f + erff(v1 * 0.70710678118654752f));
                    *(__half2*)(Hout + (size_t)(base + grow) * NTOT + col) =
                        __floats2half2_rn(v0, v1);
                } else {
                    size_t orow = SCATTER_OUT ? (size_t)g_tok[base + grow]
                                              : (size_t)(base + grow);
                    *(float2*)(OutF + orow * NTOT + col) = make_float2(v0, v1);
                }
            }
        }
    }
}

// ------------------------- launch --------------------------------------------
extern "C" void kernel_launch(void* const* d_in, const int* in_sizes, int n_in,
                              void* d_out, int out_size) {
    const float* x  = (const float*)d_in[0];
    const float* Wr = (const float*)d_in[1];
    const float* br = (const float*)d_in[2];
    const float* W1 = (const float*)d_in[3];
    const float* b1 = (const float*)d_in[4];
    const float* W2 = (const float*)d_in[5];
    const float* b2 = (const float*)d_in[6];
    float* out = (float*)d_out;

    __half *xa, *ha, *w1t, *w2t;
    cudaGetSymbolAddress((void**)&xa,  g_xa);
    cudaGetSymbolAddress((void**)&ha,  g_ha);
    cudaGetSymbolAddress((void**)&w1t, g_w1t);
    cudaGetSymbolAddress((void**)&w2t, g_w2t);

    const int SMEM_DYN = 3 * 16384;
    cudaFuncSetAttribute((const void*)k_mma<DIM, HID, true,  false>,
                         cudaFuncAttributeMaxDynamicSharedMemorySize, SMEM_DYN);
    cudaFuncSetAttribute((const void*)k_mma<HID, DIM, false, true>,
                         cudaFuncAttributeMaxDynamicSharedMemorySize, SMEM_DYN);

    k_init<<<1, 32>>>();
    k_router<<<TOK / 8, 256>>>(x, Wr, br);
    k_scan<<<1, 32>>>();
    k_scatter<<<TOK / 256, 256>>>();
    k_gather16<<<TOK, 256>>>(x);
    k_tconv<<<dim3(HID / 32, DIM / 32, NEXP), dim3(32, 8)>>>(W1, w1t, DIM, HID);
    k_tconv<<<dim3(DIM / 32, HID / 32, NEXP), dim3(32, 8)>>>(W2, w2t, HID, DIM);

    k_mma<DIM, HID, true,  false>
        <<<dim3(HID / 128, TOK / 128, NEXP), 256, SMEM_DYN>>>(xa, w1t, b1, nullptr, ha);
    k_mma<HID, DIM, false, true>
        <<<dim3(DIM / 128, TOK / 128, NEXP), 256, SMEM_DYN>>>(ha, w2t, b2, out, nullptr);
}